// round 2
// baseline (speedup 1.0000x reference)
#include <cuda_runtime.h>
#include <cstdint>
#include <math.h>

// Problem constants (fixed by the dataset instance)
constexpr int cN = 8192;    // nodes
constexpr int cD = 512;     // model units
constexpr int cH = 1024;    // hidden units
constexpr int cE = 131072;  // edges
constexpr int cF = 128;     // input features

// ---------------- scratch (device globals; no allocation allowed) ------------
constexpr size_t OFF_H    = 0;
constexpr size_t OFF_XW   = OFF_H   + (size_t)cN * cD;
constexpr size_t OFF_HA   = OFF_XW  + (size_t)cN * cD;
constexpr size_t OFF_T1   = OFF_HA  + (size_t)cN * cD;
constexpr size_t OFF_T2   = OFF_T1  + 3ull * cN * cH;
constexpr size_t OFF_QKV  = OFF_T2  + 3ull * cN * cH;
constexpr size_t OFF_DINV = OFF_QKV + 3ull * cN * cD;
constexpr size_t OFF_UTIL = OFF_DINV + cN;
constexpr size_t TOTF     = OFF_UTIL + 64;

__device__ __align__(16) float g_f[TOTF];

constexpr int ICNT = 0;            // in-degree counts      (cN)
constexpr int ICUR = cN;           // csr fill cursors      (cN)
constexpr int IPTR = 2 * cN;       // csr row pointers      (cN+1)
constexpr int ISRC = 3 * cN + 1;   // csr src node ids      (cE)
constexpr int TOTI = 3 * cN + 1 + cE;

__device__ int g_i[TOTI];

// ---------------- small helpers ----------------------------------------------
__device__ __forceinline__ uint32_t f2tf32(float x) {
    uint32_t u;
    asm("cvt.rna.tf32.f32 %0, %1;" : "=r"(u) : "f"(x));
    return u;
}

__device__ __forceinline__ void mma_tf32(float (&c)[4], const uint32_t (&a)[4],
                                         const uint32_t (&b)[2]) {
    asm volatile(
        "mma.sync.aligned.m16n8k8.row.col.f32.tf32.tf32.f32 "
        "{%0,%1,%2,%3},{%4,%5,%6,%7},{%8,%9},{%0,%1,%2,%3};"
        : "+f"(c[0]), "+f"(c[1]), "+f"(c[2]), "+f"(c[3])
        : "r"(a[0]), "r"(a[1]), "r"(a[2]), "r"(a[3]), "r"(b[0]), "r"(b[1]));
}

// ---------------- utility kernels --------------------------------------------
__global__ void zero_int_kernel(int* p, int n) {
    int i = blockIdx.x * blockDim.x + threadIdx.x;
    if (i < n) p[i] = 0;
}

__global__ void zero_f_kernel(float* p, int n) {
    int i = blockIdx.x * blockDim.x + threadIdx.x;
    if (i < n) p[i] = 0.0f;
}

__global__ void count_edges_kernel(const int* __restrict__ ei, int* __restrict__ cnt) {
    int e = blockIdx.x * blockDim.x + threadIdx.x;
    if (e < cE) atomicAdd(&cnt[ei[cE + e]], 1);
}

// 256 threads, one block. Exclusive scan of 8192 counts + dinv computation.
__global__ void scan_dinv_kernel(const int* __restrict__ cnt, int* __restrict__ ptr,
                                 float* __restrict__ dinv) {
    __shared__ int part[257];
    int t = threadIdx.x;
    int base = t * 32;
    int s = 0;
    for (int i = 0; i < 32; i++) s += cnt[base + i];
    part[t] = s;
    __syncthreads();
    if (t == 0) {
        int run = 0;
        for (int i = 0; i < 256; i++) { int v = part[i]; part[i] = run; run += v; }
        part[256] = run;
    }
    __syncthreads();
    int run = part[t];
    for (int i = 0; i < 32; i++) {
        int c = cnt[base + i];
        ptr[base + i] = run;
        run += c;
        dinv[base + i] = rsqrtf((float)c + 1.0f);
    }
    if (t == 0) ptr[cN] = part[256];
}

__global__ void fill_csr_kernel(const int* __restrict__ ei, const int* __restrict__ ptr,
                                int* __restrict__ cur, int* __restrict__ srcs) {
    int e = blockIdx.x * blockDim.x + threadIdx.x;
    if (e < cE) {
        int d = ei[cE + e];
        int p = atomicAdd(&cur[d], 1);
        srcs[ptr[d] + p] = ei[e];
    }
}

// ---------------- tf32 tensor-core GEMM --------------------------------------
// C(M x N) = act(A(M x K) @ W(K x N) + bias). BM=128, BN=64, BK=32, 256 threads.
// blockIdx.z selects a batched slab via the stride parameters.
// ACT: 0=none, 1=relu, 2=tanh
// Dynamic smem: As[2][128][36] then Bs[2][32][68]  (54272 bytes)
constexpr int GEMM_SMEM = (2 * 128 * 36 + 2 * 32 * 68) * 4;

template <int ACT>
__global__ __launch_bounds__(256) void gemm_tf32(
    const float* __restrict__ A, const float* __restrict__ W,
    const float* __restrict__ bias, float* __restrict__ C,
    int M, int K, int N, size_t sA, size_t sW, size_t sB, size_t sC) {
    extern __shared__ uint32_t smem[];
    uint32_t(*As)[128][36] = (uint32_t(*)[128][36])smem;
    uint32_t(*Bs)[32][68] = (uint32_t(*)[32][68])(smem + 2 * 128 * 36);

    int z = blockIdx.z;
    A += z * sA;
    W += z * sW;
    const float* bz = bias ? bias + z * sB : nullptr;
    C += z * sC;

    int tid = threadIdx.x;
    int lane = tid & 31, warp = tid >> 5;
    int wm = warp & 3, wn = warp >> 2;       // 4 x 2 warp grid
    int g = lane >> 2, q4 = lane & 3;

    int rowB = blockIdx.y * 128;
    int colB = blockIdx.x * 64;

    int arow = tid >> 3, ac = (tid & 7) << 2;    // A: 128 rows x 32 cols
    int brow = tid >> 4, bc = (tid & 15) << 2;   // B: 32 rows x 64 cols

    float4 aR[4];
    float4 bR[2];

    auto loadG = [&](int kt) {
#pragma unroll
        for (int i = 0; i < 4; i++)
            aR[i] = *(const float4*)&A[(size_t)(rowB + arow + i * 32) * K + kt * 32 + ac];
#pragma unroll
        for (int i = 0; i < 2; i++)
            bR[i] = *(const float4*)&W[(size_t)(kt * 32 + brow + i * 16) * N + colB + bc];
    };
    auto stS = [&](int s) {
#pragma unroll
        for (int i = 0; i < 4; i++) {
            uint4 u;
            u.x = f2tf32(aR[i].x); u.y = f2tf32(aR[i].y);
            u.z = f2tf32(aR[i].z); u.w = f2tf32(aR[i].w);
            *(uint4*)&As[s][arow + i * 32][ac] = u;
        }
#pragma unroll
        for (int i = 0; i < 2; i++) {
            uint4 u;
            u.x = f2tf32(bR[i].x); u.y = f2tf32(bR[i].y);
            u.z = f2tf32(bR[i].z); u.w = f2tf32(bR[i].w);
            *(uint4*)&Bs[s][brow + i * 16][bc] = u;
        }
    };

    float acc[2][4][4] = {};

    int KT = K >> 5;
    loadG(0);
    stS(0);
    __syncthreads();

    for (int kt = 0; kt < KT; kt++) {
        int cur = kt & 1;
        if (kt + 1 < KT) loadG(kt + 1);
#pragma unroll
        for (int ks = 0; ks < 4; ks++) {
            uint32_t af[2][4], bf[4][2];
            int k0 = ks * 8 + q4;
#pragma unroll
            for (int mt = 0; mt < 2; mt++) {
                int m = wm * 32 + mt * 16 + g;
                af[mt][0] = As[cur][m][k0];
                af[mt][1] = As[cur][m + 8][k0];
                af[mt][2] = As[cur][m][k0 + 4];
                af[mt][3] = As[cur][m + 8][k0 + 4];
            }
#pragma unroll
            for (int nt = 0; nt < 4; nt++) {
                int n = wn * 32 + nt * 8 + g;
                bf[nt][0] = Bs[cur][k0][n];
                bf[nt][1] = Bs[cur][k0 + 4][n];
            }
#pragma unroll
            for (int mt = 0; mt < 2; mt++)
#pragma unroll
                for (int nt = 0; nt < 4; nt++) mma_tf32(acc[mt][nt], af[mt], bf[nt]);
        }
        if (kt + 1 < KT) stS(cur ^ 1);
        __syncthreads();
    }

#pragma unroll
    for (int mt = 0; mt < 2; mt++) {
#pragma unroll
        for (int nt = 0; nt < 4; nt++) {
            int r0 = rowB + wm * 32 + mt * 16 + g;
            int c = colB + wn * 32 + nt * 8 + q4 * 2;
            float v00 = acc[mt][nt][0], v01 = acc[mt][nt][1];
            float v10 = acc[mt][nt][2], v11 = acc[mt][nt][3];
            if (bz) {
                float b0 = bz[c], b1 = bz[c + 1];
                v00 += b0; v01 += b1; v10 += b0; v11 += b1;
            }
            if (ACT == 1) {
                v00 = fmaxf(v00, 0.f); v01 = fmaxf(v01, 0.f);
                v10 = fmaxf(v10, 0.f); v11 = fmaxf(v11, 0.f);
            } else if (ACT == 2) {
                v00 = tanhf(v00); v01 = tanhf(v01);
                v10 = tanhf(v10); v11 = tanhf(v11);
            }
            float2 p0 = {v00, v01};
            float2 p1 = {v10, v11};
            *(float2*)&C[(size_t)r0 * N + c] = p0;
            *(float2*)&C[(size_t)(r0 + 8) * N + c] = p1;
        }
    }
}

// ---------------- GCN aggregation (gather over CSR) + tanh -------------------
// out[i,:] = tanh(b + dinv[i]^2 * xw[i,:] + sum_e dinv[src]*dinv[i]*xw[src,:])
__global__ __launch_bounds__(128) void gcn_agg_tanh(
    const float* __restrict__ xw, const float* __restrict__ bias,
    const int* __restrict__ ptr, const int* __restrict__ srcs,
    const float* __restrict__ dinv, float* __restrict__ out) {
    int i = blockIdx.x;
    int j0 = threadIdx.x << 2;  // 128 threads * 4 = 512 features
    float di = dinv[i];
    float4 bv = *(const float4*)&bias[j0];
    float4 xv = *(const float4*)&xw[(size_t)i * cD + j0];
    float ns = di * di;
    float a0 = bv.x + ns * xv.x;
    float a1 = bv.y + ns * xv.y;
    float a2 = bv.z + ns * xv.z;
    float a3 = bv.w + ns * xv.w;
    int s = ptr[i], e = ptr[i + 1];
    for (int k = s; k < e; k++) {
        int r = srcs[k];
        float w = di * dinv[r];
        float4 v = *(const float4*)&xw[(size_t)r * cD + j0];
        a0 += w * v.x; a1 += w * v.y; a2 += w * v.z; a3 += w * v.w;
    }
    float4 o;
    o.x = tanhf(a0); o.y = tanhf(a1); o.z = tanhf(a2); o.w = tanhf(a3);
    *(float4*)&out[(size_t)i * cD + j0] = o;
}

// ---------------- pair attention ---------------------------------------------
// Each query (node) attends exactly to the 128 nodes of the OTHER document in
// its pair (mask semantics of the reference). Block: 32 queries x 128 keys.
__global__ __launch_bounds__(256) void attn_core(const float* __restrict__ qkv,
                                                 float* __restrict__ out) {
    const float* Q = qkv;
    const float* Kx = qkv + (size_t)cN * cD;
    const float* V = qkv + 2 * (size_t)cN * cD;

    __shared__ __align__(16) float sQ[32][36];   // [d'][q]
    __shared__ __align__(16) float sP[128][36];  // [k][q]  scores -> probs
    __shared__ __align__(16) float sKV[4608];    // phase1: K^T [32][132]; phase3: V [128][36]

    int bx = blockIdx.x;
    int p = bx >> 3, half = (bx >> 2) & 1, qb = bx & 3;
    int q0 = p * 256 + half * 128 + qb * 32;
    int k0 = p * 256 + (half ^ 1) * 128;

    int tid = threadIdx.x;
    int ty = tid >> 5, tx = tid & 31;

    float s[4][4] = {};

    // ---- phase 1: S = Q K^T (32 x 128), D chunks of 32 ----
    for (int dc = 0; dc < 16; dc++) {
        {
            int qi = tid >> 3, d0 = (tid & 7) << 2;
            float4 v = *(const float4*)&Q[(size_t)(q0 + qi) * cD + dc * 32 + d0];
            sQ[d0][qi] = v.x; sQ[d0 + 1][qi] = v.y;
            sQ[d0 + 2][qi] = v.z; sQ[d0 + 3][qi] = v.w;
            int ki = tid >> 1, e0 = (tid & 1) << 4;
#pragma unroll
            for (int j = 0; j < 4; j++) {
                float4 kv = *(const float4*)&Kx[(size_t)(k0 + ki) * cD + dc * 32 + e0 + j * 4];
                sKV[(e0 + j * 4 + 0) * 132 + ki] = kv.x;
                sKV[(e0 + j * 4 + 1) * 132 + ki] = kv.y;
                sKV[(e0 + j * 4 + 2) * 132 + ki] = kv.z;
                sKV[(e0 + j * 4 + 3) * 132 + ki] = kv.w;
            }
        }
        __syncthreads();
#pragma unroll
        for (int d = 0; d < 32; d++) {
            float4 qv = *(const float4*)&sQ[d][ty << 2];
            float4 kv = *(const float4*)&sKV[d * 132 + (tx << 2)];
            s[0][0] += qv.x * kv.x; s[0][1] += qv.x * kv.y; s[0][2] += qv.x * kv.z; s[0][3] += qv.x * kv.w;
            s[1][0] += qv.y * kv.x; s[1][1] += qv.y * kv.y; s[1][2] += qv.y * kv.z; s[1][3] += qv.y * kv.w;
            s[2][0] += qv.z * kv.x; s[2][1] += qv.z * kv.y; s[2][2] += qv.z * kv.z; s[2][3] += qv.z * kv.w;
            s[3][0] += qv.w * kv.x; s[3][1] += qv.w * kv.y; s[3][2] += qv.w * kv.z; s[3][3] += qv.w * kv.w;
        }
        __syncthreads();
    }

    // ---- scale + store S transposed ----
    constexpr float scale = 0.0441941738241592f;  // 1/sqrt(512)
#pragma unroll
    for (int i = 0; i < 4; i++)
#pragma unroll
        for (int j = 0; j < 4; j++)
            sP[(tx << 2) + j][(ty << 2) + i] = s[i][j] * scale;
    __syncthreads();

    // ---- phase 2: softmax per query (over 128 cross-doc keys) ----
    if (tid < 32) {
        float m = -1e30f;
        for (int k = 0; k < 128; k++) m = fmaxf(m, sP[k][tid]);
        float sum = 0.f;
        for (int k = 0; k < 128; k++) {
            float e = __expf(sP[k][tid] - m);
            sP[k][tid] = e;
            sum += e;
        }
        float inv = 1.0f / sum;
        for (int k = 0; k < 128; k++) sP[k][tid] *= inv;
    }
    __syncthreads();

    // ---- phase 3: O = P V (32 x 512), D chunks of 32 ----
    for (int dc = 0; dc < 16; dc++) {
        {
            int ki = tid >> 1, e0 = (tid & 1) << 4;
#pragma unroll
            for (int j = 0; j < 4; j++) {
                float4 vv = *(const float4*)&V[(size_t)(k0 + ki) * cD + dc * 32 + e0 + j * 4];
                *(float4*)&sKV[ki * 36 + e0 + j * 4] = vv;
            }
        }
        __syncthreads();
        float o0 = 0.f, o1 = 0.f, o2 = 0.f, o3 = 0.f;
#pragma unroll 8
        for (int k = 0; k < 128; k++) {
            float4 pv = *(const float4*)&sP[k][ty << 2];
            float v = sKV[k * 36 + tx];
            o0 += pv.x * v; o1 += pv.y * v; o2 += pv.z * v; o3 += pv.w * v;
        }
        __syncthreads();
        out[(size_t)(q0 + (ty << 2) + 0) * cD + dc * 32 + tx] = o0;
        out[(size_t)(q0 + (ty << 2) + 1) * cD + dc * 32 + tx] = o1;
        out[(size_t)(q0 + (ty << 2) + 2) * cD + dc * 32 + tx] = o2;
        out[(size_t)(q0 + (ty << 2) + 3) * cD + dc * 32 + tx] = o3;
    }
}

// ---------------- fc2 (tanh) -> fc3 -> per-doc mean-pool sums ----------------
__global__ __launch_bounds__(256) void fc2pool(
    const float* __restrict__ h, const float* __restrict__ w2,
    const float* __restrict__ b2, const float* __restrict__ w3,
    const float* __restrict__ b3, float* __restrict__ util) {
    int lane = threadIdx.x & 31, wy = threadIdx.x >> 5;
    int r = blockIdx.x * 8 + wy;
    const float* hr = h + (size_t)r * cD;
    float a = b2[lane];
#pragma unroll 4
    for (int k = 0; k < cD; k += 4) {
        float4 hv = *(const float4*)&hr[k];
        a += hv.x * w2[(k + 0) * 32 + lane];
        a += hv.y * w2[(k + 1) * 32 + lane];
        a += hv.z * w2[(k + 2) * 32 + lane];
        a += hv.w * w2[(k + 3) * 32 + lane];
    }
    a = tanhf(a);
    float pc = a * w3[lane];
#pragma unroll
    for (int off = 16; off; off >>= 1) pc += __shfl_xor_sync(0xffffffffu, pc, off);
    if (lane == 0) atomicAdd(&util[r >> 7], pc + b3[0]);
}

__global__ void final_kernel(const float* __restrict__ util, const int* __restrict__ ia,
                             const int* __restrict__ ib, float* __restrict__ out) {
    int p = threadIdx.x;
    if (p < 32) {
        float d = (util[ib[p]] - util[ia[p]]) * (1.0f / 128.0f);
        out[p] = 1.0f / (1.0f + __expf(-d));
    }
}

// ---------------- launch orchestration ---------------------------------------
extern "C" void kernel_launch(void* const* d_in, const int* in_sizes, int n_in,
                              void* d_out, int out_size) {
    const float* x      = (const float*)d_in[0];
    const float* w_in   = (const float*)d_in[1];
    const float* b_in   = (const float*)d_in[2];
    const float* w_mid  = (const float*)d_in[3];
    const float* b_mid  = (const float*)d_in[4];
    const float* w_out  = (const float*)d_in[5];
    const float* b_out  = (const float*)d_in[6];
    const float* fc1_w  = (const float*)d_in[7];
    const float* fc1_b  = (const float*)d_in[8];
    const float* fc2_w  = (const float*)d_in[9];
    const float* fc2_b  = (const float*)d_in[10];
    const float* fc3_w  = (const float*)d_in[11];
    const float* fc3_b  = (const float*)d_in[12];
    const float* qkv1_w = (const float*)d_in[13];
    const float* qkv1_b = (const float*)d_in[14];
    const float* qkv2_w = (const float*)d_in[15];
    const float* qkv2_b = (const float*)d_in[16];
    const float* qkv3_w = (const float*)d_in[17];
    const float* qkv3_b = (const float*)d_in[18];
    const int* ei       = (const int*)d_in[19];
    const int* idx_a    = (const int*)d_in[22];
    const int* idx_b    = (const int*)d_in[23];

    float* F;
    int* I;
    cudaGetSymbolAddress((void**)&F, g_f);
    cudaGetSymbolAddress((void**)&I, g_i);

    // Allow >48KB dynamic smem for the GEMM (idempotent; non-stream API).
    cudaFuncSetAttribute(gemm_tf32<0>, cudaFuncAttributeMaxDynamicSharedMemorySize, GEMM_SMEM);
    cudaFuncSetAttribute(gemm_tf32<1>, cudaFuncAttributeMaxDynamicSharedMemorySize, GEMM_SMEM);
    cudaFuncSetAttribute(gemm_tf32<2>, cudaFuncAttributeMaxDynamicSharedMemorySize, GEMM_SMEM);

    float* H    = F + OFF_H;
    float* XW   = F + OFF_XW;
    float* HA   = F + OFF_HA;
    float* T1   = F + OFF_T1;
    float* T2   = F + OFF_T2;
    float* QKV  = F + OFF_QKV;
    float* DINV = F + OFF_DINV;
    float* UTIL = F + OFF_UTIL;

    // ---- CSR prep ----
    zero_int_kernel<<<(2 * cN + 255) / 256, 256>>>(I + ICNT, 2 * cN);  // cnt + cur
    count_edges_kernel<<<cE / 256, 256>>>(ei, I + ICNT);
    scan_dinv_kernel<<<1, 256>>>(I + ICNT, I + IPTR, DINV);
    fill_csr_kernel<<<cE / 256, 256>>>(ei, I + IPTR, I + ICUR, I + ISRC);

    const float* win[4] = {w_in, w_mid, w_mid, w_out};
    const float* bin[4] = {b_in, b_mid, b_mid, b_out};

    for (int layer = 0; layer < 4; layer++) {
        const float* hin = (layer == 0) ? x : H;
        int K = (layer == 0) ? cF : cD;
        // GCN linear: xw = hin @ w
        gemm_tf32<0><<<dim3(cD / 64, cN / 128, 1), 256, GEMM_SMEM>>>(
            hin, win[layer], nullptr, XW, cN, K, cD, 0, 0, 0, 0);
        // GCN aggregate + bias + tanh
        gcn_agg_tanh<<<cN, 128>>>(XW, bin[layer], I + IPTR, I + ISRC, DINV, HA);
        // q/k/v MLPs (batched z=3)
        gemm_tf32<1><<<dim3(cH / 64, cN / 128, 3), 256, GEMM_SMEM>>>(
            HA, qkv1_w, qkv1_b, T1, cN, cD, cH,
            0, (size_t)cD * cH, cH, (size_t)cN * cH);
        gemm_tf32<1><<<dim3(cH / 64, cN / 128, 3), 256, GEMM_SMEM>>>(
            T1, qkv2_w, qkv2_b, T2, cN, cH, cH,
            (size_t)cN * cH, (size_t)cH * cH, cH, (size_t)cN * cH);
        gemm_tf32<1><<<dim3(cD / 64, cN / 128, 3), 256, GEMM_SMEM>>>(
            T2, qkv3_w, qkv3_b, QKV, cN, cH, cD,
            (size_t)cN * cH, (size_t)cH * cD, cD, (size_t)cN * cD);
        // pairwise cross-document attention
        attn_core<<<cN / 32, 256>>>(QKV, H);
    }

    // ---- head ----
    gemm_tf32<2><<<dim3(cD / 64, cN / 128, 1), 256, GEMM_SMEM>>>(
        H, fc1_w, fc1_b, HA, cN, cD, cD, 0, 0, 0, 0);
    zero_f_kernel<<<1, 64>>>(UTIL, 64);
    fc2pool<<<cN / 8, 256>>>(HA, fc2_w, fc2_b, fc3_w, fc3_b, UTIL);
    final_kernel<<<1, 32>>>(UTIL, idx_a, idx_b, (float*)d_out);
}

// round 3
// speedup vs baseline: 1.4769x; 1.4769x over previous
#include <cuda_runtime.h>
#include <cuda_bf16.h>
#include <cstdint>
#include <math.h>

// Problem constants (fixed by the dataset instance)
constexpr int cN = 8192;    // nodes
constexpr int cD = 512;     // model units
constexpr int cH = 1024;    // hidden units
constexpr int cE = 131072;  // edges
constexpr int cF = 128;     // input features

// ---------------- scratch (device globals; no allocation allowed) ------------
constexpr size_t OFF_H    = 0;
constexpr size_t OFF_XW   = OFF_H   + (size_t)cN * cD;
constexpr size_t OFF_HA   = OFF_XW  + (size_t)cN * cD;
constexpr size_t OFF_T1   = OFF_HA  + (size_t)cN * cD;
constexpr size_t OFF_T2   = OFF_T1  + 3ull * cN * cH;
constexpr size_t OFF_QKV  = OFF_T2  + 3ull * cN * cH;
constexpr size_t OFF_DINV = OFF_QKV + 3ull * cN * cD;
constexpr size_t OFF_UTIL = OFF_DINV + cN;
constexpr size_t TOTF     = OFF_UTIL + 64;

__device__ __align__(16) float g_f[TOTF];

constexpr int ICNT = 0;            // in-degree counts      (cN)
constexpr int ICUR = cN;           // csr fill cursors      (cN)
constexpr int IPTR = 2 * cN;       // csr row pointers      (cN+1)
constexpr int ISRC = 3 * cN + 1;   // csr src node ids      (cE)
constexpr int TOTI = 3 * cN + 1 + cE;

__device__ int g_i[TOTI];

// Packed bf16-pair weights: layout [K/2][N] uint32, pair = (k even, k odd)
constexpr size_t PW_IN  = 0;
constexpr size_t PW_MID = PW_IN  + (size_t)cF * cD / 2;
constexpr size_t PW_OUT = PW_MID + (size_t)cD * cD / 2;
constexpr size_t PW_FC1 = PW_OUT + (size_t)cD * cD / 2;
constexpr size_t PW_Q1  = PW_FC1 + (size_t)cD * cD / 2;
constexpr size_t PW_Q2  = PW_Q1  + 3ull * cD * cH / 2;
constexpr size_t PW_Q3  = PW_Q2  + 3ull * cH * cH / 2;
constexpr size_t TOTW   = PW_Q3  + 3ull * cH * cD / 2;

__device__ __align__(16) uint32_t g_w[TOTW];

// ---------------- small helpers ----------------------------------------------
__device__ __forceinline__ uint32_t pack_bf16(float lo, float hi) {
    __nv_bfloat162 v = __floats2bfloat162_rn(lo, hi);
    return *(uint32_t*)&v;
}

__device__ __forceinline__ void mma_bf16(float (&c)[4], const uint32_t (&a)[4],
                                         const uint32_t (&b)[2]) {
    asm volatile(
        "mma.sync.aligned.m16n8k16.row.col.f32.bf16.bf16.f32 "
        "{%0,%1,%2,%3},{%4,%5,%6,%7},{%8,%9},{%0,%1,%2,%3};"
        : "+f"(c[0]), "+f"(c[1]), "+f"(c[2]), "+f"(c[3])
        : "r"(a[0]), "r"(a[1]), "r"(a[2]), "r"(a[3]), "r"(b[0]), "r"(b[1]));
}

// ---------------- utility kernels --------------------------------------------
__global__ void zero_int_kernel(int* p, int n) {
    int i = blockIdx.x * blockDim.x + threadIdx.x;
    if (i < n) p[i] = 0;
}

__global__ void zero_f_kernel(float* p, int n) {
    int i = blockIdx.x * blockDim.x + threadIdx.x;
    if (i < n) p[i] = 0.0f;
}

// Pack fp32 weights [K][N] -> bf16-pair words [K/2][N]
__global__ void pack_w_kernel(const float* __restrict__ W, uint32_t* __restrict__ Wp,
                              int N, int total) {
    int i = blockIdx.x * blockDim.x + threadIdx.x;
    if (i < total) {
        int kp = i / N, n = i - kp * N;
        Wp[i] = pack_bf16(W[(size_t)(2 * kp) * N + n], W[(size_t)(2 * kp + 1) * N + n]);
    }
}

__global__ void count_edges_kernel(const int* __restrict__ ei, int* __restrict__ cnt) {
    int e = blockIdx.x * blockDim.x + threadIdx.x;
    if (e < cE) atomicAdd(&cnt[ei[cE + e]], 1);
}

// 256 threads, one block. Exclusive scan of 8192 counts + dinv computation.
__global__ void scan_dinv_kernel(const int* __restrict__ cnt, int* __restrict__ ptr,
                                 float* __restrict__ dinv) {
    __shared__ int part[257];
    int t = threadIdx.x;
    int base = t * 32;
    int s = 0;
    for (int i = 0; i < 32; i++) s += cnt[base + i];
    part[t] = s;
    __syncthreads();
    if (t == 0) {
        int run = 0;
        for (int i = 0; i < 256; i++) { int v = part[i]; part[i] = run; run += v; }
        part[256] = run;
    }
    __syncthreads();
    int run = part[t];
    for (int i = 0; i < 32; i++) {
        int c = cnt[base + i];
        ptr[base + i] = run;
        run += c;
        dinv[base + i] = rsqrtf((float)c + 1.0f);
    }
    if (t == 0) ptr[cN] = part[256];
}

__global__ void fill_csr_kernel(const int* __restrict__ ei, const int* __restrict__ ptr,
                                int* __restrict__ cur, int* __restrict__ srcs) {
    int e = blockIdx.x * blockDim.x + threadIdx.x;
    if (e < cE) {
        int d = ei[cE + e];
        int p = atomicAdd(&cur[d], 1);
        srcs[ptr[d] + p] = ei[e];
    }
}

// ---------------- bf16 tensor-core GEMM --------------------------------------
// C(M x N) = act(A(M x K) @ W(K x N) + bias).
// A: fp32 row-major (converted to bf16 pairs during staging).
// Wp: pre-packed bf16 pairs [K/2][N] uint32.
// BM=128, BN=128, BK=32, 256 threads (8 warps: 4 row-groups x 2 col-groups,
// warp tile 32x64 via 2x8 m16n8k16 tiles). ACT: 0=none, 1=relu, 2=tanh.
template <int ACT>
__global__ __launch_bounds__(256) void gemm_bf16(
    const float* __restrict__ A, const uint32_t* __restrict__ Wp,
    const float* __restrict__ bias, float* __restrict__ C,
    int M, int K, int N, size_t sA, size_t sW, size_t sB, size_t sC) {
    __shared__ __align__(16) uint32_t As[2][128][20];  // bf16 pairs along k (16 used)
    __shared__ __align__(16) uint32_t Bs[2][16][136];  // bf16 pairs along k x 128 cols

    int z = blockIdx.z;
    A += z * sA;
    Wp += z * sW;
    const float* bz = bias ? bias + z * sB : nullptr;
    C += z * sC;

    int tid = threadIdx.x;
    int lane = tid & 31, warp = tid >> 5;
    int wm = warp & 3, wn = warp >> 2;  // 4 x 2 warp grid
    int g = lane >> 2, q4 = lane & 3;

    int rowB = blockIdx.y * 128;
    int colB = blockIdx.x * 128;

    // A staging: row = tid>>1, k-offset = (tid&1)*16  (16 floats -> 8 packed words)
    int arow = tid >> 1, akoff = (tid & 1) * 16;
    // B staging: kr = tid>>4 (packed row 0..15), nc = (tid&15)*8 (8 words)
    int brow = tid >> 4, bcol = (tid & 15) * 8;

    float4 aR[4];
    uint4 bR[2];

    auto loadG = [&](int kt) {
        const float* ap = &A[(size_t)(rowB + arow) * K + kt * 32 + akoff];
#pragma unroll
        for (int i = 0; i < 4; i++) aR[i] = *(const float4*)&ap[i * 4];
        const uint32_t* bp = &Wp[(size_t)(kt * 16 + brow) * N + colB + bcol];
        bR[0] = *(const uint4*)&bp[0];
        bR[1] = *(const uint4*)&bp[4];
    };
    auto stS = [&](int s) {
        uint32_t u[8];
#pragma unroll
        for (int i = 0; i < 4; i++) {
            u[2 * i + 0] = pack_bf16(aR[i].x, aR[i].y);
            u[2 * i + 1] = pack_bf16(aR[i].z, aR[i].w);
        }
        *(uint4*)&As[s][arow][akoff / 2 + 0] = *(uint4*)&u[0];
        *(uint4*)&As[s][arow][akoff / 2 + 4] = *(uint4*)&u[4];
        *(uint4*)&Bs[s][brow][bcol + 0] = bR[0];
        *(uint4*)&Bs[s][brow][bcol + 4] = bR[1];
    };

    float acc[2][8][4] = {};

    int KT = K >> 5;
    loadG(0);
    stS(0);
    __syncthreads();

    for (int kt = 0; kt < KT; kt++) {
        int cur = kt & 1;
        if (kt + 1 < KT) loadG(kt + 1);
#pragma unroll
        for (int c = 0; c < 2; c++) {  // two k16 chunks per BK=32 tile
            uint32_t af[2][4], bf[8][2];
            int kq = c * 8 + q4;
#pragma unroll
            for (int mt = 0; mt < 2; mt++) {
                int m = wm * 32 + mt * 16 + g;
                af[mt][0] = As[cur][m][kq];
                af[mt][1] = As[cur][m + 8][kq];
                af[mt][2] = As[cur][m][kq + 4];
                af[mt][3] = As[cur][m + 8][kq + 4];
            }
#pragma unroll
            for (int nt = 0; nt < 8; nt++) {
                int n = wn * 64 + nt * 8 + g;
                bf[nt][0] = Bs[cur][kq][n];
                bf[nt][1] = Bs[cur][kq + 4][n];
            }
#pragma unroll
            for (int mt = 0; mt < 2; mt++)
#pragma unroll
                for (int nt = 0; nt < 8; nt++) mma_bf16(acc[mt][nt], af[mt], bf[nt]);
        }
        if (kt + 1 < KT) stS(cur ^ 1);
        __syncthreads();
    }

#pragma unroll
    for (int mt = 0; mt < 2; mt++) {
#pragma unroll
        for (int nt = 0; nt < 8; nt++) {
            int r0 = rowB + wm * 32 + mt * 16 + g;
            int c = colB + wn * 64 + nt * 8 + q4 * 2;
            float v00 = acc[mt][nt][0], v01 = acc[mt][nt][1];
            float v10 = acc[mt][nt][2], v11 = acc[mt][nt][3];
            if (bz) {
                float b0 = bz[c], b1 = bz[c + 1];
                v00 += b0; v01 += b1; v10 += b0; v11 += b1;
            }
            if (ACT == 1) {
                v00 = fmaxf(v00, 0.f); v01 = fmaxf(v01, 0.f);
                v10 = fmaxf(v10, 0.f); v11 = fmaxf(v11, 0.f);
            } else if (ACT == 2) {
                v00 = tanhf(v00); v01 = tanhf(v01);
                v10 = tanhf(v10); v11 = tanhf(v11);
            }
            float2 p0 = {v00, v01};
            float2 p1 = {v10, v11};
            *(float2*)&C[(size_t)r0 * N + c] = p0;
            *(float2*)&C[(size_t)(r0 + 8) * N + c] = p1;
        }
    }
}

// ---------------- GCN aggregation (gather over CSR) + tanh -------------------
// out[i,:] = tanh(b + dinv[i]^2 * xw[i,:] + sum_e dinv[src]*dinv[i]*xw[src,:])
__global__ __launch_bounds__(128) void gcn_agg_tanh(
    const float* __restrict__ xw, const float* __restrict__ bias,
    const int* __restrict__ ptr, const int* __restrict__ srcs,
    const float* __restrict__ dinv, float* __restrict__ out) {
    int i = blockIdx.x;
    int j0 = threadIdx.x << 2;  // 128 threads * 4 = 512 features
    float di = dinv[i];
    float4 bv = *(const float4*)&bias[j0];
    float4 xv = *(const float4*)&xw[(size_t)i * cD + j0];
    float ns = di * di;
    float a0 = bv.x + ns * xv.x;
    float a1 = bv.y + ns * xv.y;
    float a2 = bv.z + ns * xv.z;
    float a3 = bv.w + ns * xv.w;
    int s = ptr[i], e = ptr[i + 1];
    for (int k = s; k < e; k++) {
        int r = srcs[k];
        float w = di * dinv[r];
        float4 v = *(const float4*)&xw[(size_t)r * cD + j0];
        a0 += w * v.x; a1 += w * v.y; a2 += w * v.z; a3 += w * v.w;
    }
    float4 o;
    o.x = tanhf(a0); o.y = tanhf(a1); o.z = tanhf(a2); o.w = tanhf(a3);
    *(float4*)&out[(size_t)i * cD + j0] = o;
}

// ---------------- pair attention ---------------------------------------------
// Each query (node) attends exactly to the 128 nodes of the OTHER document in
// its pair (mask semantics of the reference). Block: 32 queries x 128 keys.
__global__ __launch_bounds__(256) void attn_core(const float* __restrict__ qkv,
                                                 float* __restrict__ out) {
    const float* Q = qkv;
    const float* Kx = qkv + (size_t)cN * cD;
    const float* V = qkv + 2 * (size_t)cN * cD;

    __shared__ __align__(16) float sQ[32][36];   // [d'][q]
    __shared__ __align__(16) float sP[128][36];  // [k][q]  scores -> probs
    __shared__ __align__(16) float sKV[4608];    // phase1: K^T [32][132]; phase3: V [128][36]

    int bx = blockIdx.x;
    int p = bx >> 3, half = (bx >> 2) & 1, qb = bx & 3;
    int q0 = p * 256 + half * 128 + qb * 32;
    int k0 = p * 256 + (half ^ 1) * 128;

    int tid = threadIdx.x;
    int ty = tid >> 5, tx = tid & 31;

    float s[4][4] = {};

    // ---- phase 1: S = Q K^T (32 x 128), D chunks of 32 ----
    for (int dc = 0; dc < 16; dc++) {
        {
            int qi = tid >> 3, d0 = (tid & 7) << 2;
            float4 v = *(const float4*)&Q[(size_t)(q0 + qi) * cD + dc * 32 + d0];
            sQ[d0][qi] = v.x; sQ[d0 + 1][qi] = v.y;
            sQ[d0 + 2][qi] = v.z; sQ[d0 + 3][qi] = v.w;
            int ki = tid >> 1, e0 = (tid & 1) << 4;
#pragma unroll
            for (int j = 0; j < 4; j++) {
                float4 kv = *(const float4*)&Kx[(size_t)(k0 + ki) * cD + dc * 32 + e0 + j * 4];
                sKV[(e0 + j * 4 + 0) * 132 + ki] = kv.x;
                sKV[(e0 + j * 4 + 1) * 132 + ki] = kv.y;
                sKV[(e0 + j * 4 + 2) * 132 + ki] = kv.z;
                sKV[(e0 + j * 4 + 3) * 132 + ki] = kv.w;
            }
        }
        __syncthreads();
#pragma unroll
        for (int d = 0; d < 32; d++) {
            float4 qv = *(const float4*)&sQ[d][ty << 2];
            float4 kv = *(const float4*)&sKV[d * 132 + (tx << 2)];
            s[0][0] += qv.x * kv.x; s[0][1] += qv.x * kv.y; s[0][2] += qv.x * kv.z; s[0][3] += qv.x * kv.w;
            s[1][0] += qv.y * kv.x; s[1][1] += qv.y * kv.y; s[1][2] += qv.y * kv.z; s[1][3] += qv.y * kv.w;
            s[2][0] += qv.z * kv.x; s[2][1] += qv.z * kv.y; s[2][2] += qv.z * kv.z; s[2][3] += qv.z * kv.w;
            s[3][0] += qv.w * kv.x; s[3][1] += qv.w * kv.y; s[3][2] += qv.w * kv.z; s[3][3] += qv.w * kv.w;
        }
        __syncthreads();
    }

    // ---- scale + store S transposed ----
    constexpr float scale = 0.0441941738241592f;  // 1/sqrt(512)
#pragma unroll
    for (int i = 0; i < 4; i++)
#pragma unroll
        for (int j = 0; j < 4; j++)
            sP[(tx << 2) + j][(ty << 2) + i] = s[i][j] * scale;
    __syncthreads();

    // ---- phase 2: softmax per query (over 128 cross-doc keys) ----
    if (tid < 32) {
        float m = -1e30f;
        for (int k = 0; k < 128; k++) m = fmaxf(m, sP[k][tid]);
        float sum = 0.f;
        for (int k = 0; k < 128; k++) {
            float e = __expf(sP[k][tid] - m);
            sP[k][tid] = e;
            sum += e;
        }
        float inv = 1.0f / sum;
        for (int k = 0; k < 128; k++) sP[k][tid] *= inv;
    }
    __syncthreads();

    // ---- phase 3: O = P V (32 x 512), D chunks of 32 ----
    for (int dc = 0; dc < 16; dc++) {
        {
            int ki = tid >> 1, e0 = (tid & 1) << 4;
#pragma unroll
            for (int j = 0; j < 4; j++) {
                float4 vv = *(const float4*)&V[(size_t)(k0 + ki) * cD + dc * 32 + e0 + j * 4];
                *(float4*)&sKV[ki * 36 + e0 + j * 4] = vv;
            }
        }
        __syncthreads();
        float o0 = 0.f, o1 = 0.f, o2 = 0.f, o3 = 0.f;
#pragma unroll 8
        for (int k = 0; k < 128; k++) {
            float4 pv = *(const float4*)&sP[k][ty << 2];
            float v = sKV[k * 36 + tx];
            o0 += pv.x * v; o1 += pv.y * v; o2 += pv.z * v; o3 += pv.w * v;
        }
        __syncthreads();
        out[(size_t)(q0 + (ty << 2) + 0) * cD + dc * 32 + tx] = o0;
        out[(size_t)(q0 + (ty << 2) + 1) * cD + dc * 32 + tx] = o1;
        out[(size_t)(q0 + (ty << 2) + 2) * cD + dc * 32 + tx] = o2;
        out[(size_t)(q0 + (ty << 2) + 3) * cD + dc * 32 + tx] = o3;
    }
}

// ---------------- fc2 (tanh) -> fc3 -> per-doc mean-pool sums ----------------
__global__ __launch_bounds__(256) void fc2pool(
    const float* __restrict__ h, const float* __restrict__ w2,
    const float* __restrict__ b2, const float* __restrict__ w3,
    const float* __restrict__ b3, float* __restrict__ util) {
    int lane = threadIdx.x & 31, wy = threadIdx.x >> 5;
    int r = blockIdx.x * 8 + wy;
    const float* hr = h + (size_t)r * cD;
    float a = b2[lane];
#pragma unroll 4
    for (int k = 0; k < cD; k += 4) {
        float4 hv = *(const float4*)&hr[k];
        a += hv.x * w2[(k + 0) * 32 + lane];
        a += hv.y * w2[(k + 1) * 32 + lane];
        a += hv.z * w2[(k + 2) * 32 + lane];
        a += hv.w * w2[(k + 3) * 32 + lane];
    }
    a = tanhf(a);
    float pc = a * w3[lane];
#pragma unroll
    for (int off = 16; off; off >>= 1) pc += __shfl_xor_sync(0xffffffffu, pc, off);
    if (lane == 0) atomicAdd(&util[r >> 7], pc + b3[0]);
}

__global__ void final_kernel(const float* __restrict__ util, const int* __restrict__ ia,
                             const int* __restrict__ ib, float* __restrict__ out) {
    int p = threadIdx.x;
    if (p < 32) {
        float d = (util[ib[p]] - util[ia[p]]) * (1.0f / 128.0f);
        out[p] = 1.0f / (1.0f + __expf(-d));
    }
}

// ---------------- launch orchestration ---------------------------------------
static inline void pack_w(const float* W, uint32_t* Wp, int Krows, int N) {
    int total = Krows / 2 * N;
    pack_w_kernel<<<(total + 255) / 256, 256>>>(W, Wp, N, total);
}

extern "C" void kernel_launch(void* const* d_in, const int* in_sizes, int n_in,
                              void* d_out, int out_size) {
    const float* x      = (const float*)d_in[0];
    const float* w_in   = (const float*)d_in[1];
    const float* b_in   = (const float*)d_in[2];
    const float* w_mid  = (const float*)d_in[3];
    const float* b_mid  = (const float*)d_in[4];
    const float* w_out  = (const float*)d_in[5];
    const float* b_out  = (const float*)d_in[6];
    const float* fc1_w  = (const float*)d_in[7];
    const float* fc1_b  = (const float*)d_in[8];
    const float* fc2_w  = (const float*)d_in[9];
    const float* fc2_b  = (const float*)d_in[10];
    const float* fc3_w  = (const float*)d_in[11];
    const float* fc3_b  = (const float*)d_in[12];
    const float* qkv1_w = (const float*)d_in[13];
    const float* qkv1_b = (const float*)d_in[14];
    const float* qkv2_w = (const float*)d_in[15];
    const float* qkv2_b = (const float*)d_in[16];
    const float* qkv3_w = (const float*)d_in[17];
    const float* qkv3_b = (const float*)d_in[18];
    const int* ei       = (const int*)d_in[19];
    const int* idx_a    = (const int*)d_in[22];
    const int* idx_b    = (const int*)d_in[23];

    float* F;
    int* I;
    uint32_t* Wb;
    cudaGetSymbolAddress((void**)&F, g_f);
    cudaGetSymbolAddress((void**)&I, g_i);
    cudaGetSymbolAddress((void**)&Wb, g_w);

    float* H    = F + OFF_H;
    float* XW   = F + OFF_XW;
    float* HA   = F + OFF_HA;
    float* T1   = F + OFF_T1;
    float* T2   = F + OFF_T2;
    float* QKV  = F + OFF_QKV;
    float* DINV = F + OFF_DINV;
    float* UTIL = F + OFF_UTIL;

    // ---- pre-pack weights into bf16-pair layout (cheap; once per replay) ----
    pack_w(w_in,   Wb + PW_IN,  cF, cD);
    pack_w(w_mid,  Wb + PW_MID, cD, cD);
    pack_w(w_out,  Wb + PW_OUT, cD, cD);
    pack_w(fc1_w,  Wb + PW_FC1, cD, cD);
    pack_w(qkv1_w, Wb + PW_Q1,  3 * cD, cH);   // pairs never cross matrices (K even)
    pack_w(qkv2_w, Wb + PW_Q2,  3 * cH, cH);
    pack_w(qkv3_w, Wb + PW_Q3,  3 * cH, cD);

    // ---- CSR prep ----
    zero_int_kernel<<<(2 * cN + 255) / 256, 256>>>(I + ICNT, 2 * cN);  // cnt + cur
    count_edges_kernel<<<cE / 256, 256>>>(ei, I + ICNT);
    scan_dinv_kernel<<<1, 256>>>(I + ICNT, I + IPTR, DINV);
    fill_csr_kernel<<<cE / 256, 256>>>(ei, I + IPTR, I + ICUR, I + ISRC);

    const uint32_t* winp[4] = {Wb + PW_IN, Wb + PW_MID, Wb + PW_MID, Wb + PW_OUT};
    const float*    bin[4]  = {b_in, b_mid, b_mid, b_out};

    for (int layer = 0; layer < 4; layer++) {
        const float* hin = (layer == 0) ? x : H;
        int K = (layer == 0) ? cF : cD;
        // GCN linear: xw = hin @ w
        gemm_bf16<0><<<dim3(cD / 128, cN / 128, 1), 256>>>(
            hin, winp[layer], nullptr, XW, cN, K, cD, 0, 0, 0, 0);
        // GCN aggregate + bias + tanh
        gcn_agg_tanh<<<cN, 128>>>(XW, bin[layer], I + IPTR, I + ISRC, DINV, HA);
        // q/k/v MLPs (batched z=3)
        gemm_bf16<1><<<dim3(cH / 128, cN / 128, 3), 256>>>(
            HA, Wb + PW_Q1, qkv1_b, T1, cN, cD, cH,
            0, (size_t)cD * cH / 2, cH, (size_t)cN * cH);
        gemm_bf16<1><<<dim3(cH / 128, cN / 128, 3), 256>>>(
            T1, Wb + PW_Q2, qkv2_b, T2, cN, cH, cH,
            (size_t)cN * cH, (size_t)cH * cH / 2, cH, (size_t)cN * cH);
        gemm_bf16<1><<<dim3(cD / 128, cN / 128, 3), 256>>>(
            T2, Wb + PW_Q3, qkv3_b, QKV, cN, cH, cD,
            (size_t)cN * cH, (size_t)cH * cD / 2, cD, (size_t)cN * cD);
        // pairwise cross-document attention
        attn_core<<<cN / 32, 256>>>(QKV, H);
    }

    // ---- head ----
    gemm_bf16<2><<<dim3(cD / 128, cN / 128, 1), 256>>>(
        H, Wb + PW_FC1, fc1_b, HA, cN, cD, cD, 0, 0, 0, 0);
    zero_f_kernel<<<1, 64>>>(UTIL, 64);
    fc2pool<<<cN / 8, 256>>>(HA, fc2_w, fc2_b, fc3_w, fc3_b, UTIL);
    final_kernel<<<1, 32>>>(UTIL, idx_a, idx_b, (float*)d_out);
}

// round 4
// speedup vs baseline: 1.6407x; 1.1109x over previous
#include <cuda_runtime.h>
#include <cuda_bf16.h>
#include <cstdint>
#include <math.h>

// Problem constants (fixed by the dataset instance)
constexpr int cN = 8192;    // nodes
constexpr int cD = 512;     // model units
constexpr int cH = 1024;    // hidden units
constexpr int cE = 131072;  // edges
constexpr int cF = 128;     // input features

// ---------------- scratch (device globals; no allocation allowed) ------------
constexpr size_t OFF_H    = 0;
constexpr size_t OFF_XW   = OFF_H   + (size_t)cN * cD;
constexpr size_t OFF_HA   = OFF_XW  + (size_t)cN * cD;
constexpr size_t OFF_T1   = OFF_HA  + (size_t)cN * cD;
constexpr size_t OFF_T2   = OFF_T1  + 3ull * cN * cH;
constexpr size_t OFF_QKV  = OFF_T2  + 3ull * cN * cH;
constexpr size_t OFF_DINV = OFF_QKV + 3ull * cN * cD;
constexpr size_t OFF_UTIL = OFF_DINV + cN;
constexpr size_t TOTF     = OFF_UTIL + 64;

__device__ __align__(16) float g_f[TOTF];

constexpr int ICNT = 0;            // in-degree counts      (cN)
constexpr int ICUR = cN;           // csr fill cursors      (cN)
constexpr int IPTR = 2 * cN;       // csr row pointers      (cN+1)
constexpr int ISRC = 3 * cN + 1;   // csr src node ids      (cE)
constexpr int TOTI = 3 * cN + 1 + cE;

__device__ int g_i[TOTI];

// Packed bf16-pair weights: layout [z][N][K/2] uint32, word = (k even, k odd)
constexpr size_t PW_IN  = 0;
constexpr size_t PW_MID = PW_IN  + (size_t)cF * cD / 2;
constexpr size_t PW_OUT = PW_MID + (size_t)cD * cD / 2;
constexpr size_t PW_FC1 = PW_OUT + (size_t)cD * cD / 2;
constexpr size_t PW_Q1  = PW_FC1 + (size_t)cD * cD / 2;
constexpr size_t PW_Q2  = PW_Q1  + 3ull * cD * cH / 2;
constexpr size_t PW_Q3  = PW_Q2  + 3ull * cH * cH / 2;
constexpr size_t TOTW   = PW_Q3  + 3ull * cH * cD / 2;

__device__ __align__(16) uint32_t g_w[TOTW];

// ---------------- small helpers ----------------------------------------------
__device__ __forceinline__ uint32_t pack_bf16(float lo, float hi) {
    __nv_bfloat162 v = __floats2bfloat162_rn(lo, hi);
    return *(uint32_t*)&v;
}

__device__ __forceinline__ void mma_bf16(float (&c)[4], const uint32_t (&a)[4],
                                         const uint32_t (&b)[2]) {
    asm volatile(
        "mma.sync.aligned.m16n8k16.row.col.f32.bf16.bf16.f32 "
        "{%0,%1,%2,%3},{%4,%5,%6,%7},{%8,%9},{%0,%1,%2,%3};"
        : "+f"(c[0]), "+f"(c[1]), "+f"(c[2]), "+f"(c[3])
        : "r"(a[0]), "r"(a[1]), "r"(a[2]), "r"(a[3]), "r"(b[0]), "r"(b[1]));
}

__device__ __forceinline__ void ldsm4(uint32_t (&r)[4], const uint32_t* p) {
    uint32_t a = (uint32_t)__cvta_generic_to_shared(p);
    asm volatile("ldmatrix.sync.aligned.m8n8.x4.shared.b16 {%0,%1,%2,%3}, [%4];"
                 : "=r"(r[0]), "=r"(r[1]), "=r"(r[2]), "=r"(r[3]) : "r"(a));
}

// A-operand ldmatrix lane offsets (m16 x k16 tile):
//   row = ((lane>>3)&1)*8 + (lane&7), colpair = (lane>>4)*4
// B-operand (n-major) ldmatrix lane offsets (n16 x k16 -> two n8 fragments):
//   row = ((lane>>4)<<3) + (lane&7), colpair = ((lane>>3)&1)*4

// ---------------- utility kernels --------------------------------------------
__global__ void zero_int_kernel(int* p, int n) {
    int i = blockIdx.x * blockDim.x + threadIdx.x;
    if (i < n) p[i] = 0;
}

__global__ void zero_f_kernel(float* p, int n) {
    int i = blockIdx.x * blockDim.x + threadIdx.x;
    if (i < n) p[i] = 0.0f;
}

// Pack fp32 weights [z][K][N] -> bf16-pair words [z][N][K/2]
__global__ void pack_w_kernel(const float* __restrict__ W, uint32_t* __restrict__ Wp,
                              int K, int N, int total) {
    int i = blockIdx.x * blockDim.x + threadIdx.x;
    if (i >= total) return;
    int kp2 = K >> 1;
    int z = i / (N * kp2);
    int rem = i - z * N * kp2;
    int n = rem / kp2;
    int kp = rem - n * kp2;
    const float* Wz = W + (size_t)z * K * N;
    Wp[i] = pack_bf16(Wz[(size_t)(2 * kp) * N + n], Wz[(size_t)(2 * kp + 1) * N + n]);
}

__global__ void count_edges_kernel(const int* __restrict__ ei, int* __restrict__ cnt) {
    int e = blockIdx.x * blockDim.x + threadIdx.x;
    if (e < cE) atomicAdd(&cnt[ei[cE + e]], 1);
}

// 256 threads, one block. Exclusive scan of 8192 counts + dinv computation.
__global__ void scan_dinv_kernel(const int* __restrict__ cnt, int* __restrict__ ptr,
                                 float* __restrict__ dinv) {
    __shared__ int part[257];
    int t = threadIdx.x;
    int base = t * 32;
    int s = 0;
    for (int i = 0; i < 32; i++) s += cnt[base + i];
    part[t] = s;
    __syncthreads();
    if (t == 0) {
        int run = 0;
        for (int i = 0; i < 256; i++) { int v = part[i]; part[i] = run; run += v; }
        part[256] = run;
    }
    __syncthreads();
    int run = part[t];
    for (int i = 0; i < 32; i++) {
        int c = cnt[base + i];
        ptr[base + i] = run;
        run += c;
        dinv[base + i] = rsqrtf((float)c + 1.0f);
    }
    if (t == 0) ptr[cN] = part[256];
}

__global__ void fill_csr_kernel(const int* __restrict__ ei, const int* __restrict__ ptr,
                                int* __restrict__ cur, int* __restrict__ srcs) {
    int e = blockIdx.x * blockDim.x + threadIdx.x;
    if (e < cE) {
        int d = ei[cE + e];
        int p = atomicAdd(&cur[d], 1);
        srcs[ptr[d] + p] = ei[e];
    }
}

// ---------------- bf16 tensor-core GEMM (ldmatrix fragments) ------------------
// C(M x N) = act(A(M x K) @ W(K x N) + bias).
// A: fp32 row-major (converted to bf16 pairs during staging).
// Wp: pre-packed bf16 pairs [N][K/2] uint32 (n-major!).
// BM=128, BN=128, BK=32, 256 threads (8 warps 4x2, warp tile 32x64).
template <int ACT>
__global__ __launch_bounds__(256) void gemm_bf16(
    const float* __restrict__ A, const uint32_t* __restrict__ Wp,
    const float* __restrict__ bias, float* __restrict__ C,
    int M, int K, int N, size_t sA, size_t sW, size_t sB, size_t sC) {
    __shared__ __align__(16) uint32_t As[2][128][20];  // [m][kpair]
    __shared__ __align__(16) uint32_t Bs[2][128][20];  // [n][kpair]

    int z = blockIdx.z;
    A += z * sA;
    Wp += z * sW;
    const float* bz = bias ? bias + z * sB : nullptr;
    C += z * sC;

    int tid = threadIdx.x;
    int lane = tid & 31, warp = tid >> 5;
    int wm = warp & 3, wn = warp >> 2;  // 4 x 2 warp grid
    int g = lane >> 2, q4 = lane & 3;

    int rowB = blockIdx.y * 128;
    int colB = blockIdx.x * 128;

    // ldmatrix lane offsets
    int a_ro = ((lane >> 3) & 1) * 8 + (lane & 7);
    int a_co = (lane >> 4) * 4;
    int b_ro = ((lane >> 4) << 3) + (lane & 7);
    int b_co = ((lane >> 3) & 1) * 4;

    // staging maps
    int arow = tid >> 1, akp = (tid & 1) * 8;  // A: 2 threads/row, 8 kpairs each
    int bn = tid >> 1, bkp = (tid & 1) * 8;    // B: 2 threads/row(n), 8 kpairs each

    float4 aR[4];
    uint4 bR[2];

    int kp2 = K >> 1;

    auto loadG = [&](int kt) {
        const float* ap = &A[(size_t)(rowB + arow) * K + kt * 32 + akp * 2];
#pragma unroll
        for (int i = 0; i < 4; i++) aR[i] = *(const float4*)&ap[i * 4];
        const uint32_t* bp = &Wp[(size_t)(colB + bn) * kp2 + kt * 16 + bkp];
        bR[0] = *(const uint4*)&bp[0];
        bR[1] = *(const uint4*)&bp[4];
    };
    auto stS = [&](int s) {
        uint32_t u[8];
#pragma unroll
        for (int i = 0; i < 4; i++) {
            u[2 * i + 0] = pack_bf16(aR[i].x, aR[i].y);
            u[2 * i + 1] = pack_bf16(aR[i].z, aR[i].w);
        }
        *(uint4*)&As[s][arow][akp + 0] = *(uint4*)&u[0];
        *(uint4*)&As[s][arow][akp + 4] = *(uint4*)&u[4];
        *(uint4*)&Bs[s][bn][bkp + 0] = bR[0];
        *(uint4*)&Bs[s][bn][bkp + 4] = bR[1];
    };

    float acc[2][8][4] = {};

    int KT = K >> 5;
    loadG(0);
    stS(0);
    __syncthreads();

    for (int kt = 0; kt < KT; kt++) {
        int cur = kt & 1;
        if (kt + 1 < KT) loadG(kt + 1);
#pragma unroll
        for (int c = 0; c < 2; c++) {  // two k16 chunks per BK=32
            uint32_t af[2][4];
            ldsm4(af[0], &As[cur][wm * 32 + a_ro][c * 8 + a_co]);
            ldsm4(af[1], &As[cur][wm * 32 + 16 + a_ro][c * 8 + a_co]);
            uint32_t bf[8][2];
#pragma unroll
            for (int nt2 = 0; nt2 < 4; nt2++) {
                uint32_t r[4];
                ldsm4(r, &Bs[cur][wn * 64 + nt2 * 16 + b_ro][c * 8 + b_co]);
                bf[2 * nt2][0] = r[0]; bf[2 * nt2][1] = r[1];
                bf[2 * nt2 + 1][0] = r[2]; bf[2 * nt2 + 1][1] = r[3];
            }
#pragma unroll
            for (int mt = 0; mt < 2; mt++)
#pragma unroll
                for (int nt = 0; nt < 8; nt++) mma_bf16(acc[mt][nt], af[mt], bf[nt]);
        }
        if (kt + 1 < KT) stS(cur ^ 1);
        __syncthreads();
    }

#pragma unroll
    for (int mt = 0; mt < 2; mt++) {
#pragma unroll
        for (int nt = 0; nt < 8; nt++) {
            int r0 = rowB + wm * 32 + mt * 16 + g;
            int c = colB + wn * 64 + nt * 8 + q4 * 2;
            float v00 = acc[mt][nt][0], v01 = acc[mt][nt][1];
            float v10 = acc[mt][nt][2], v11 = acc[mt][nt][3];
            if (bz) {
                float b0 = bz[c], b1 = bz[c + 1];
                v00 += b0; v01 += b1; v10 += b0; v11 += b1;
            }
            if (ACT == 1) {
                v00 = fmaxf(v00, 0.f); v01 = fmaxf(v01, 0.f);
                v10 = fmaxf(v10, 0.f); v11 = fmaxf(v11, 0.f);
            } else if (ACT == 2) {
                v00 = tanhf(v00); v01 = tanhf(v01);
                v10 = tanhf(v10); v11 = tanhf(v11);
            }
            float2 p0 = {v00, v01};
            float2 p1 = {v10, v11};
            *(float2*)&C[(size_t)r0 * N + c] = p0;
            *(float2*)&C[(size_t)(r0 + 8) * N + c] = p1;
        }
    }
}

// ---------------- GCN aggregation (gather over CSR) + tanh -------------------
__global__ __launch_bounds__(128) void gcn_agg_tanh(
    const float* __restrict__ xw, const float* __restrict__ bias,
    const int* __restrict__ ptr, const int* __restrict__ srcs,
    const float* __restrict__ dinv, float* __restrict__ out) {
    int i = blockIdx.x;
    int j0 = threadIdx.x << 2;
    float di = dinv[i];
    float4 bv = *(const float4*)&bias[j0];
    float4 xv = *(const float4*)&xw[(size_t)i * cD + j0];
    float ns = di * di;
    float a0 = bv.x + ns * xv.x;
    float a1 = bv.y + ns * xv.y;
    float a2 = bv.z + ns * xv.z;
    float a3 = bv.w + ns * xv.w;
    int s = ptr[i], e = ptr[i + 1];
    for (int k = s; k < e; k++) {
        int r = srcs[k];
        float w = di * dinv[r];
        float4 v = *(const float4*)&xw[(size_t)r * cD + j0];
        a0 += w * v.x; a1 += w * v.y; a2 += w * v.z; a3 += w * v.w;
    }
    float4 o;
    o.x = tanhf(a0); o.y = tanhf(a1); o.z = tanhf(a2); o.w = tanhf(a3);
    *(float4*)&out[(size_t)i * cD + j0] = o;
}

// ---------------- tensor-core pair attention ---------------------------------
// One block per (pair, half): 128 queries x 128 cross-doc keys, D=512.
// Dynamic smem layout (uint32 words):
//   phase1: Qs[128][36] @0, Ks[128][36] @4608
//   phase2/3: P[128][68] @0, Vs[64][68] @8704, stats(float[256]) @13056
constexpr int ATT_SMEM_W = 128 * 68 + 64 * 68 + 256;   // 13312 words
constexpr int ATT_SMEM = ATT_SMEM_W * 4;               // 53248 bytes

__global__ __launch_bounds__(256) void attn_tc(const float* __restrict__ qkv,
                                               float* __restrict__ out) {
    extern __shared__ __align__(16) uint32_t sm[];
    uint32_t(*Qs)[36] = (uint32_t(*)[36])sm;
    uint32_t(*Ks)[36] = (uint32_t(*)[36])(sm + 128 * 36);
    uint32_t(*P)[68] = (uint32_t(*)[68])sm;
    uint32_t(*Vs)[68] = (uint32_t(*)[68])(sm + 128 * 68);
    float* stats = (float*)(sm + 128 * 68 + 64 * 68);  // [2][128]

    const float* Q = qkv;
    const float* Kx = qkv + (size_t)cN * cD;
    const float* V = qkv + 2 * (size_t)cN * cD;

    int p = blockIdx.x >> 1, half = blockIdx.x & 1;
    int q0 = p * 256 + half * 128;
    int k0 = p * 256 + (half ^ 1) * 128;

    int tid = threadIdx.x;
    int lane = tid & 31, warp = tid >> 5;
    int wm = warp & 3, wn = warp >> 2;  // 4 x 2
    int g = lane >> 2, q4 = lane & 3;

    int a_ro = ((lane >> 3) & 1) * 8 + (lane & 7);
    int a_co = (lane >> 4) * 4;
    int b_ro = ((lane >> 4) << 3) + (lane & 7);
    int b_co = ((lane >> 3) & 1) * 4;

    // ---- phase 1: S = Q K^T (128x128), accumulate over 8 chunks of 64 dims ----
    float acc[2][8][4] = {};
    int srow = tid >> 1, spair = (tid & 1) * 16;  // staging: 2 thr/row, 16 pairs each
    for (int dc = 0; dc < 8; dc++) {
        {
            const float* qp = &Q[(size_t)(q0 + srow) * cD + dc * 64 + spair * 2];
            const float* kp = &Kx[(size_t)(k0 + srow) * cD + dc * 64 + spair * 2];
            uint32_t uq[16], uk[16];
#pragma unroll
            for (int i = 0; i < 8; i++) {
                float4 a = *(const float4*)&qp[i * 4];
                float4 b = *(const float4*)&kp[i * 4];
                uq[2 * i] = pack_bf16(a.x, a.y); uq[2 * i + 1] = pack_bf16(a.z, a.w);
                uk[2 * i] = pack_bf16(b.x, b.y); uk[2 * i + 1] = pack_bf16(b.z, b.w);
            }
#pragma unroll
            for (int i = 0; i < 4; i++) {
                *(uint4*)&Qs[srow][spair + 4 * i] = *(uint4*)&uq[4 * i];
                *(uint4*)&Ks[srow][spair + 4 * i] = *(uint4*)&uk[4 * i];
            }
        }
        __syncthreads();
#pragma unroll
        for (int c = 0; c < 4; c++) {
            uint32_t af[2][4];
            ldsm4(af[0], &Qs[wm * 32 + a_ro][c * 8 + a_co]);
            ldsm4(af[1], &Qs[wm * 32 + 16 + a_ro][c * 8 + a_co]);
            uint32_t bf[8][2];
#pragma unroll
            for (int nt2 = 0; nt2 < 4; nt2++) {
                uint32_t r[4];
                ldsm4(r, &Ks[wn * 64 + nt2 * 16 + b_ro][c * 8 + b_co]);
                bf[2 * nt2][0] = r[0]; bf[2 * nt2][1] = r[1];
                bf[2 * nt2 + 1][0] = r[2]; bf[2 * nt2 + 1][1] = r[3];
            }
#pragma unroll
            for (int mt = 0; mt < 2; mt++)
#pragma unroll
                for (int nt = 0; nt < 8; nt++) mma_bf16(acc[mt][nt], af[mt], bf[nt]);
        }
        __syncthreads();
    }

    // ---- phase 2: softmax over 128 keys per query ----
    constexpr float scale = 0.0441941738241592f;  // 1/sqrt(512)
#pragma unroll
    for (int mt = 0; mt < 2; mt++)
#pragma unroll
        for (int nt = 0; nt < 8; nt++)
#pragma unroll
            for (int j = 0; j < 4; j++) acc[mt][nt][j] *= scale;

    float mx[2][2];
#pragma unroll
    for (int mt = 0; mt < 2; mt++) {
        float m0 = -1e30f, m1 = -1e30f;
#pragma unroll
        for (int nt = 0; nt < 8; nt++) {
            m0 = fmaxf(m0, fmaxf(acc[mt][nt][0], acc[mt][nt][1]));
            m1 = fmaxf(m1, fmaxf(acc[mt][nt][2], acc[mt][nt][3]));
        }
#pragma unroll
        for (int d = 1; d < 4; d <<= 1) {
            m0 = fmaxf(m0, __shfl_xor_sync(0xffffffffu, m0, d));
            m1 = fmaxf(m1, __shfl_xor_sync(0xffffffffu, m1, d));
        }
        mx[mt][0] = m0; mx[mt][1] = m1;
    }
    if (q4 == 0) {
#pragma unroll
        for (int mt = 0; mt < 2; mt++) {
            int r = wm * 32 + mt * 16 + g;
            stats[wn * 128 + r] = mx[mt][0];
            stats[wn * 128 + r + 8] = mx[mt][1];
        }
    }
    __syncthreads();
    float rmax[2][2], rsum[2][2];
#pragma unroll
    for (int mt = 0; mt < 2; mt++) {
        int r = wm * 32 + mt * 16 + g;
        rmax[mt][0] = fmaxf(stats[r], stats[128 + r]);
        rmax[mt][1] = fmaxf(stats[r + 8], stats[128 + r + 8]);
    }
#pragma unroll
    for (int mt = 0; mt < 2; mt++) {
        float s0 = 0.f, s1 = 0.f;
#pragma unroll
        for (int nt = 0; nt < 8; nt++) {
            acc[mt][nt][0] = __expf(acc[mt][nt][0] - rmax[mt][0]);
            acc[mt][nt][1] = __expf(acc[mt][nt][1] - rmax[mt][0]);
            acc[mt][nt][2] = __expf(acc[mt][nt][2] - rmax[mt][1]);
            acc[mt][nt][3] = __expf(acc[mt][nt][3] - rmax[mt][1]);
            s0 += acc[mt][nt][0] + acc[mt][nt][1];
            s1 += acc[mt][nt][2] + acc[mt][nt][3];
        }
#pragma unroll
        for (int d = 1; d < 4; d <<= 1) {
            s0 += __shfl_xor_sync(0xffffffffu, s0, d);
            s1 += __shfl_xor_sync(0xffffffffu, s1, d);
        }
        rsum[mt][0] = s0; rsum[mt][1] = s1;
    }
    __syncthreads();  // all max reads done before stats reuse
    if (q4 == 0) {
#pragma unroll
        for (int mt = 0; mt < 2; mt++) {
            int r = wm * 32 + mt * 16 + g;
            stats[wn * 128 + r] = rsum[mt][0];
            stats[wn * 128 + r + 8] = rsum[mt][1];
        }
    }
    __syncthreads();
#pragma unroll
    for (int mt = 0; mt < 2; mt++) {
        int r = wm * 32 + mt * 16 + g;
        float i0 = 1.0f / (stats[r] + stats[128 + r]);
        float i1 = 1.0f / (stats[r + 8] + stats[128 + r + 8]);
#pragma unroll
        for (int nt = 0; nt < 8; nt++) {
            int kp = wn * 32 + nt * 4 + q4;
            P[r][kp] = pack_bf16(acc[mt][nt][0] * i0, acc[mt][nt][1] * i0);
            P[r + 8][kp] = pack_bf16(acc[mt][nt][2] * i1, acc[mt][nt][3] * i1);
        }
    }
    __syncthreads();

    // ---- phase 3: O = P V (128 x 512), n chunks of 64 dims ----
    int vkp = tid >> 2, vd0 = (tid & 3) * 16;
    for (int nc = 0; nc < 8; nc++) {
        {
            const float* v0 = &V[(size_t)(k0 + 2 * vkp) * cD + nc * 64 + vd0];
            const float* v1 = v0 + cD;
#pragma unroll
            for (int i = 0; i < 4; i++) {
                float4 a = *(const float4*)&v0[i * 4];
                float4 b = *(const float4*)&v1[i * 4];
                Vs[vd0 + 4 * i + 0][vkp] = pack_bf16(a.x, b.x);
                Vs[vd0 + 4 * i + 1][vkp] = pack_bf16(a.y, b.y);
                Vs[vd0 + 4 * i + 2][vkp] = pack_bf16(a.z, b.z);
                Vs[vd0 + 4 * i + 3][vkp] = pack_bf16(a.w, b.w);
            }
        }
        __syncthreads();
        float o[2][4][4] = {};
#pragma unroll
        for (int c = 0; c < 8; c++) {  // 128 keys = 8 k16 chunks
            uint32_t af[2][4];
            ldsm4(af[0], &P[wm * 32 + a_ro][c * 8 + a_co]);
            ldsm4(af[1], &P[wm * 32 + 16 + a_ro][c * 8 + a_co]);
            uint32_t bf[4][2];
#pragma unroll
            for (int nt2 = 0; nt2 < 2; nt2++) {
                uint32_t r[4];
                ldsm4(r, &Vs[wn * 32 + nt2 * 16 + b_ro][c * 8 + b_co]);
                bf[2 * nt2][0] = r[0]; bf[2 * nt2][1] = r[1];
                bf[2 * nt2 + 1][0] = r[2]; bf[2 * nt2 + 1][1] = r[3];
            }
#pragma unroll
            for (int mt = 0; mt < 2; mt++)
#pragma unroll
                for (int nt = 0; nt < 4; nt++) mma_bf16(o[mt][nt], af[mt], bf[nt]);
        }
#pragma unroll
        for (int mt = 0; mt < 2; mt++)
#pragma unroll
            for (int nt = 0; nt < 4; nt++) {
                int r = q0 + wm * 32 + mt * 16 + g;
                int cidx = nc * 64 + wn * 32 + nt * 8 + q4 * 2;
                float2 p0 = {o[mt][nt][0], o[mt][nt][1]};
                float2 p1 = {o[mt][nt][2], o[mt][nt][3]};
                *(float2*)&out[(size_t)r * cD + cidx] = p0;
                *(float2*)&out[(size_t)(r + 8) * cD + cidx] = p1;
            }
        __syncthreads();
    }
}

// ---------------- fc2 (tanh) -> fc3 -> per-doc mean-pool sums ----------------
__global__ __launch_bounds__(256) void fc2pool(
    const float* __restrict__ h, const float* __restrict__ w2,
    const float* __restrict__ b2, const float* __restrict__ w3,
    const float* __restrict__ b3, float* __restrict__ util) {
    int lane = threadIdx.x & 31, wy = threadIdx.x >> 5;
    int r = blockIdx.x * 8 + wy;
    const float* hr = h + (size_t)r * cD;
    float a = b2[lane];
#pragma unroll 4
    for (int k = 0; k < cD; k += 4) {
        float4 hv = *(const float4*)&hr[k];
        a += hv.x * w2[(k + 0) * 32 + lane];
        a += hv.y * w2[(k + 1) * 32 + lane];
        a += hv.z * w2[(k + 2) * 32 + lane];
        a += hv.w * w2[(k + 3) * 32 + lane];
    }
    a = tanhf(a);
    float pc = a * w3[lane];
#pragma unroll
    for (int off = 16; off; off >>= 1) pc += __shfl_xor_sync(0xffffffffu, pc, off);
    if (lane == 0) atomicAdd(&util[r >> 7], pc + b3[0]);
}

__global__ void final_kernel(const float* __restrict__ util, const int* __restrict__ ia,
                             const int* __restrict__ ib, float* __restrict__ out) {
    int p = threadIdx.x;
    if (p < 32) {
        float d = (util[ib[p]] - util[ia[p]]) * (1.0f / 128.0f);
        out[p] = 1.0f / (1.0f + __expf(-d));
    }
}

// ---------------- launch orchestration ---------------------------------------
static inline void pack_w(const float* W, uint32_t* Wp, int K, int N, int zc) {
    int total = zc * (K / 2) * N;
    pack_w_kernel<<<(total + 255) / 256, 256>>>(W, Wp, K, N, total);
}

extern "C" void kernel_launch(void* const* d_in, const int* in_sizes, int n_in,
                              void* d_out, int out_size) {
    const float* x      = (const float*)d_in[0];
    const float* w_in   = (const float*)d_in[1];
    const float* b_in   = (const float*)d_in[2];
    const float* w_mid  = (const float*)d_in[3];
    const float* b_mid  = (const float*)d_in[4];
    const float* w_out  = (const float*)d_in[5];
    const float* b_out  = (const float*)d_in[6];
    const float* fc1_w  = (const float*)d_in[7];
    const float* fc1_b  = (const float*)d_in[8];
    const float* fc2_w  = (const float*)d_in[9];
    const float* fc2_b  = (const float*)d_in[10];
    const float* fc3_w  = (const float*)d_in[11];
    const float* fc3_b  = (const float*)d_in[12];
    const float* qkv1_w = (const float*)d_in[13];
    const float* qkv1_b = (const float*)d_in[14];
    const float* qkv2_w = (const float*)d_in[15];
    const float* qkv2_b = (const float*)d_in[16];
    const float* qkv3_w = (const float*)d_in[17];
    const float* qkv3_b = (const float*)d_in[18];
    const int* ei       = (const int*)d_in[19];
    const int* idx_a    = (const int*)d_in[22];
    const int* idx_b    = (const int*)d_in[23];

    float* F;
    int* I;
    uint32_t* Wb;
    cudaGetSymbolAddress((void**)&F, g_f);
    cudaGetSymbolAddress((void**)&I, g_i);
    cudaGetSymbolAddress((void**)&Wb, g_w);

    cudaFuncSetAttribute(attn_tc, cudaFuncAttributeMaxDynamicSharedMemorySize, ATT_SMEM);

    float* H    = F + OFF_H;
    float* XW   = F + OFF_XW;
    float* HA   = F + OFF_HA;
    float* T1   = F + OFF_T1;
    float* T2   = F + OFF_T2;
    float* QKV  = F + OFF_QKV;
    float* DINV = F + OFF_DINV;
    float* UTIL = F + OFF_UTIL;

    // ---- pre-pack weights into bf16-pair [N][K/2] layout ----
    pack_w(w_in,   Wb + PW_IN,  cF, cD, 1);
    pack_w(w_mid,  Wb + PW_MID, cD, cD, 1);
    pack_w(w_out,  Wb + PW_OUT, cD, cD, 1);
    pack_w(fc1_w,  Wb + PW_FC1, cD, cD, 1);
    pack_w(qkv1_w, Wb + PW_Q1,  cD, cH, 3);
    pack_w(qkv2_w, Wb + PW_Q2,  cH, cH, 3);
    pack_w(qkv3_w, Wb + PW_Q3,  cH, cD, 3);

    // ---- CSR prep ----
    zero_int_kernel<<<(2 * cN + 255) / 256, 256>>>(I + ICNT, 2 * cN);
    count_edges_kernel<<<cE / 256, 256>>>(ei, I + ICNT);
    scan_dinv_kernel<<<1, 256>>>(I + ICNT, I + IPTR, DINV);
    fill_csr_kernel<<<cE / 256, 256>>>(ei, I + IPTR, I + ICUR, I + ISRC);

    const uint32_t* winp[4] = {Wb + PW_IN, Wb + PW_MID, Wb + PW_MID, Wb + PW_OUT};
    const float*    bin[4]  = {b_in, b_mid, b_mid, b_out};

    for (int layer = 0; layer < 4; layer++) {
        const float* hin = (layer == 0) ? x : H;
        int K = (layer == 0) ? cF : cD;
        gemm_bf16<0><<<dim3(cD / 128, cN / 128, 1), 256>>>(
            hin, winp[layer], nullptr, XW, cN, K, cD, 0, 0, 0, 0);
        gcn_agg_tanh<<<cN, 128>>>(XW, bin[layer], I + IPTR, I + ISRC, DINV, HA);
        gemm_bf16<1><<<dim3(cH / 128, cN / 128, 3), 256>>>(
            HA, Wb + PW_Q1, qkv1_b, T1, cN, cD, cH,
            0, (size_t)cH * cD / 2, cH, (size_t)cN * cH);
        gemm_bf16<1><<<dim3(cH / 128, cN / 128, 3), 256>>>(
            T1, Wb + PW_Q2, qkv2_b, T2, cN, cH, cH,
            (size_t)cN * cH, (size_t)cH * cH / 2, cH, (size_t)cN * cH);
        gemm_bf16<1><<<dim3(cD / 128, cN / 128, 3), 256>>>(
            T2, Wb + PW_Q3, qkv3_b, QKV, cN, cH, cD,
            (size_t)cN * cH, (size_t)cD * cH / 2, cD, (size_t)cN * cD);
        attn_tc<<<64, 256, ATT_SMEM>>>(QKV, H);
    }

    // ---- head ----
    gemm_bf16<2><<<dim3(cD / 128, cN / 128, 1), 256>>>(
        H, Wb + PW_FC1, fc1_b, HA, cN, cD, cD, 0, 0, 0, 0);
    zero_f_kernel<<<1, 64>>>(UTIL, 64);
    fc2pool<<<cN / 8, 256>>>(HA, fc2_w, fc2_b, fc3_w, fc3_b, UTIL);
    final_kernel<<<1, 32>>>(UTIL, idx_a, idx_b, (float*)d_out);
}

// round 6
// speedup vs baseline: 1.9344x; 1.1790x over previous
#include <cuda_runtime.h>
#include <cuda_bf16.h>
#include <cstdint>
#include <math.h>

// Problem constants (fixed by the dataset instance)
constexpr int cN = 8192;    // nodes
constexpr int cD = 512;     // model units
constexpr int cH = 1024;    // hidden units
constexpr int cE = 131072;  // edges
constexpr int cF = 128;     // input features

constexpr int cDw = cD / 2;  // 256 packed words per row
constexpr int cHw = cH / 2;  // 512
constexpr int cFw = cF / 2;  // 64

// ---------------- scratch (device globals; no allocation allowed) ------------
constexpr size_t UP_XP   = 0;
constexpr size_t UP_H    = UP_XP  + (size_t)cN * cFw;
constexpr size_t UP_XW   = UP_H   + (size_t)cN * cDw;
constexpr size_t UP_HA   = UP_XW  + (size_t)cN * cDw;
constexpr size_t UP_T1   = UP_HA  + (size_t)cN * cDw;
constexpr size_t UP_T2   = UP_T1  + 3ull * cN * cHw;
constexpr size_t UP_QKV  = UP_T2  + 3ull * cN * cHw;
constexpr size_t TOTU    = UP_QKV + 3ull * cN * cDw;

__device__ __align__(16) uint32_t g_u[TOTU];

constexpr size_t OFF_HAF  = 0;
constexpr size_t OFF_DINV = OFF_HAF + (size_t)cN * cD;
constexpr size_t OFF_UTIL = OFF_DINV + cN;
constexpr size_t TOTF     = OFF_UTIL + 64;

__device__ __align__(16) float g_f[TOTF];

constexpr int ICNT = 0;
constexpr int ICUR = cN;
constexpr int IPTR = 2 * cN;
constexpr int ISRC = 3 * cN + 1;
constexpr int TOTI = 3 * cN + 1 + cE;

__device__ int g_i[TOTI];

// Packed bf16-pair weights: layout [z][N][K/2] uint32 (n-major, K-pairs)
constexpr size_t PW_IN  = 0;
constexpr size_t PW_MID = PW_IN  + (size_t)cF * cD / 2;
constexpr size_t PW_OUT = PW_MID + (size_t)cD * cD / 2;
constexpr size_t PW_FC1 = PW_OUT + (size_t)cD * cD / 2;
constexpr size_t PW_Q1  = PW_FC1 + (size_t)cD * cD / 2;
constexpr size_t PW_Q2  = PW_Q1  + 3ull * cD * cH / 2;
constexpr size_t PW_Q3  = PW_Q2  + 3ull * cH * cH / 2;
constexpr size_t TOTW   = PW_Q3  + 3ull * cH * cD / 2;

__device__ __align__(16) uint32_t g_w[TOTW];

// ---------------- small helpers ----------------------------------------------
__device__ __forceinline__ uint32_t pack_bf16(float lo, float hi) {
    __nv_bfloat162 v = __floats2bfloat162_rn(lo, hi);
    return *(uint32_t*)&v;
}

__device__ __forceinline__ float2 unpack_bf16(uint32_t u) {
    return __bfloat1622float2(*(__nv_bfloat162*)&u);
}

__device__ __forceinline__ void mma_bf16(float (&c)[4], const uint32_t (&a)[4],
                                         const uint32_t (&b)[2]) {
    asm volatile(
        "mma.sync.aligned.m16n8k16.row.col.f32.bf16.bf16.f32 "
        "{%0,%1,%2,%3},{%4,%5,%6,%7},{%8,%9},{%0,%1,%2,%3};"
        : "+f"(c[0]), "+f"(c[1]), "+f"(c[2]), "+f"(c[3])
        : "r"(a[0]), "r"(a[1]), "r"(a[2]), "r"(a[3]), "r"(b[0]), "r"(b[1]));
}

__device__ __forceinline__ void ldsm4(uint32_t (&r)[4], const uint32_t* p) {
    uint32_t a = (uint32_t)__cvta_generic_to_shared(p);
    asm volatile("ldmatrix.sync.aligned.m8n8.x4.shared.b16 {%0,%1,%2,%3}, [%4];"
                 : "=r"(r[0]), "=r"(r[1]), "=r"(r[2]), "=r"(r[3]) : "r"(a));
}

__device__ __forceinline__ void cp_async16(const void* smem_dst, const void* gsrc) {
    uint32_t d = (uint32_t)__cvta_generic_to_shared(smem_dst);
    asm volatile("cp.async.cg.shared.global [%0], [%1], 16;" :: "r"(d), "l"(gsrc)
                 : "memory");
}
#define CP_COMMIT() asm volatile("cp.async.commit_group;" ::: "memory")
#define CP_WAIT(n)  asm volatile("cp.async.wait_group %0;" :: "n"(n) : "memory")

// ---------------- utility kernels --------------------------------------------
__global__ void zero_int_kernel(int* p, int n) {
    int i = blockIdx.x * blockDim.x + threadIdx.x;
    if (i < n) p[i] = 0;
}

constexpr int XPn = cN * cFw;
constexpr size_t PACK_TOT = (size_t)XPn + TOTW;

// One kernel: pack x + all weights into bf16-pair layouts.
__global__ void pack_all_kernel(const float* __restrict__ x,
                                const float* __restrict__ w_in,
                                const float* __restrict__ w_mid,
                                const float* __restrict__ w_out,
                                const float* __restrict__ fc1_w,
                                const float* __restrict__ q1,
                                const float* __restrict__ q2,
                                const float* __restrict__ q3,
                                uint32_t* __restrict__ XP,
                                uint32_t* __restrict__ Wb) {
    size_t i = (size_t)blockIdx.x * blockDim.x + threadIdx.x;
    if (i >= PACK_TOT) return;
    if (i < (size_t)XPn) {
        XP[i] = pack_bf16(x[2 * i], x[2 * i + 1]);
        return;
    }
    size_t j = i - XPn;
    const float* W;
    size_t lo;
    int K, N;
    if (j < PW_MID)      { W = w_in;  lo = PW_IN;  K = cF; N = cD; }
    else if (j < PW_OUT) { W = w_mid; lo = PW_MID; K = cD; N = cD; }
    else if (j < PW_FC1) { W = w_out; lo = PW_OUT; K = cD; N = cD; }
    else if (j < PW_Q1)  { W = fc1_w; lo = PW_FC1; K = cD; N = cD; }
    else if (j < PW_Q2)  { W = q1;    lo = PW_Q1;  K = cD; N = cH; }
    else if (j < PW_Q3)  { W = q2;    lo = PW_Q2;  K = cH; N = cH; }
    else                 { W = q3;    lo = PW_Q3;  K = cH; N = cD; }
    size_t l = j - lo;
    int kp2 = K >> 1;
    int z = (int)(l / ((size_t)N * kp2));
    int rem = (int)(l - (size_t)z * N * kp2);
    int n = rem / kp2;
    int kp = rem - n * kp2;
    const float* Wz = W + (size_t)z * K * N;
    Wb[j] = pack_bf16(Wz[(size_t)(2 * kp) * N + n], Wz[(size_t)(2 * kp + 1) * N + n]);
}

__global__ void count_edges_kernel(const int* __restrict__ ei, int* __restrict__ cnt) {
    int e = blockIdx.x * blockDim.x + threadIdx.x;
    if (e < cE) atomicAdd(&cnt[ei[cE + e]], 1);
}

__global__ void scan_dinv_kernel(const int* __restrict__ cnt, int* __restrict__ ptr,
                                 float* __restrict__ dinv) {
    __shared__ int part[257];
    int t = threadIdx.x;
    int base = t * 32;
    int s = 0;
    for (int i = 0; i < 32; i++) s += cnt[base + i];
    part[t] = s;
    __syncthreads();
    if (t == 0) {
        int run = 0;
        for (int i = 0; i < 256; i++) { int v = part[i]; part[i] = run; run += v; }
        part[256] = run;
    }
    __syncthreads();
    int run = part[t];
    for (int i = 0; i < 32; i++) {
        int c = cnt[base + i];
        ptr[base + i] = run;
        run += c;
        dinv[base + i] = rsqrtf((float)c + 1.0f);
    }
    if (t == 0) ptr[cN] = part[256];
}

__global__ void fill_csr_kernel(const int* __restrict__ ei, const int* __restrict__ ptr,
                                int* __restrict__ cur, int* __restrict__ srcs) {
    int e = blockIdx.x * blockDim.x + threadIdx.x;
    if (e < cE) {
        int d = ei[cE + e];
        int p = atomicAdd(&cur[d], 1);
        srcs[ptr[d] + p] = ei[e];
    }
}

// ---------------- warp-MMA bf16 GEMM (cp.async, BK=64) ------------------------
// C(M x N) = act(A @ W + bias). A: packed bf16 [M][K/2]; Wp: [z][N][K/2].
// Tile 128x128, BK=64 (32 words), 256 threads (8 warps 4x2, warp tile 32x64).
// ACT: 0=none 1=relu 2=tanh.  OUTF: 0=fp32, 1=packed bf16.
constexpr int GEMM_DYN = 2 * 2 * 128 * 36 * 4;  // 73728 bytes

template <int ACT, int OUTF>
__global__ __launch_bounds__(256) void gemm_wm(
    const uint32_t* __restrict__ Ap, const uint32_t* __restrict__ Wp,
    const float* __restrict__ bias, void* __restrict__ Cout,
    int Kp2, int N, size_t sA, size_t sW, size_t sB, size_t sC) {
    extern __shared__ __align__(16) uint32_t sh[];
    uint32_t(*As)[128][36] = (uint32_t(*)[128][36])sh;
    uint32_t(*Bs)[128][36] = (uint32_t(*)[128][36])(sh + 2 * 128 * 36);

    int z = blockIdx.z;
    Ap += z * sA;
    Wp += z * sW;
    const float* bz = bias ? bias + z * sB : nullptr;

    int tid = threadIdx.x;
    int lane = tid & 31, warp = tid >> 5;
    int wm = warp & 3, wn = warp >> 2;  // 4 x 2 warp grid
    int g = lane >> 2, q4 = lane & 3;

    int rowB = blockIdx.y * 128;
    int colB = blockIdx.x * 128;

    // ldmatrix lane offsets
    int a_ro = ((lane >> 3) & 1) * 8 + (lane & 7);
    int a_co = (lane >> 4) * 4;
    int b_ro = ((lane >> 4) << 3) + (lane & 7);
    int b_co = ((lane >> 3) & 1) * 4;

    // staging: 128 rows x 32 words per tile; thread -> row tid>>1, words (tid&1)*16
    int srow = tid >> 1, sw0 = (tid & 1) * 16;

    auto stage = [&](int buf, int kt) {
        const uint32_t* as = &Ap[(size_t)(rowB + srow) * Kp2 + kt * 32 + sw0];
        const uint32_t* bs = &Wp[(size_t)(colB + srow) * Kp2 + kt * 32 + sw0];
#pragma unroll
        for (int i = 0; i < 4; i++) {
            cp_async16(&As[buf][srow][sw0 + 4 * i], as + 4 * i);
            cp_async16(&Bs[buf][srow][sw0 + 4 * i], bs + 4 * i);
        }
        CP_COMMIT();
    };

    float acc[2][8][4] = {};

    int KT = Kp2 >> 5;  // BK=64 -> 32 words per tile row
    stage(0, 0);

    for (int kt = 0; kt < KT; kt++) {
        int cur = kt & 1;
        if (kt + 1 < KT) {
            stage(cur ^ 1, kt + 1);
            CP_WAIT(1);
        } else {
            CP_WAIT(0);
        }
        __syncthreads();
#pragma unroll
        for (int c = 0; c < 4; c++) {  // four k16 chunks per BK=64
            uint32_t af[2][4];
            ldsm4(af[0], &As[cur][wm * 32 + a_ro][c * 8 + a_co]);
            ldsm4(af[1], &As[cur][wm * 32 + 16 + a_ro][c * 8 + a_co]);
            uint32_t bf[8][2];
#pragma unroll
            for (int nt2 = 0; nt2 < 4; nt2++) {
                uint32_t r[4];
                ldsm4(r, &Bs[cur][wn * 64 + nt2 * 16 + b_ro][c * 8 + b_co]);
                bf[2 * nt2][0] = r[0]; bf[2 * nt2][1] = r[1];
                bf[2 * nt2 + 1][0] = r[2]; bf[2 * nt2 + 1][1] = r[3];
            }
#pragma unroll
            for (int mt = 0; mt < 2; mt++)
#pragma unroll
                for (int nt = 0; nt < 8; nt++) mma_bf16(acc[mt][nt], af[mt], bf[nt]);
        }
        __syncthreads();
    }

    // epilogue
#pragma unroll
    for (int mt = 0; mt < 2; mt++) {
#pragma unroll
        for (int nt = 0; nt < 8; nt++) {
            int r0 = rowB + wm * 32 + mt * 16 + g;
            int c = colB + wn * 64 + nt * 8 + q4 * 2;
            float v00 = acc[mt][nt][0], v01 = acc[mt][nt][1];
            float v10 = acc[mt][nt][2], v11 = acc[mt][nt][3];
            if (bz) {
                float b0 = bz[c], b1 = bz[c + 1];
                v00 += b0; v01 += b1; v10 += b0; v11 += b1;
            }
            if (ACT == 1) {
                v00 = fmaxf(v00, 0.f); v01 = fmaxf(v01, 0.f);
                v10 = fmaxf(v10, 0.f); v11 = fmaxf(v11, 0.f);
            } else if (ACT == 2) {
                v00 = tanhf(v00); v01 = tanhf(v01);
                v10 = tanhf(v10); v11 = tanhf(v11);
            }
            if (OUTF == 1) {
                uint32_t* Cw = (uint32_t*)Cout + z * sC;
                Cw[(size_t)r0 * (N >> 1) + (c >> 1)] = pack_bf16(v00, v01);
                Cw[(size_t)(r0 + 8) * (N >> 1) + (c >> 1)] = pack_bf16(v10, v11);
            } else {
                float* Cf = (float*)Cout + z * sC;
                float2 p0 = {v00, v01};
                float2 p1 = {v10, v11};
                *(float2*)&Cf[(size_t)r0 * N + c] = p0;
                *(float2*)&Cf[(size_t)(r0 + 8) * N + c] = p1;
            }
        }
    }
}

// ---------------- GCN aggregation (packed bf16 in/out) ------------------------
__global__ __launch_bounds__(128) void gcn_agg_tanh(
    const uint32_t* __restrict__ xw, const float* __restrict__ bias,
    const int* __restrict__ ptr, const int* __restrict__ srcs,
    const float* __restrict__ dinv, uint32_t* __restrict__ out) {
    int i = blockIdx.x;
    int w0 = threadIdx.x * 2;
    float di = dinv[i];
    float4 bv = *(const float4*)&bias[w0 * 2];
    uint2 xv = *(const uint2*)&xw[(size_t)i * cDw + w0];
    float2 x0 = unpack_bf16(xv.x), x1 = unpack_bf16(xv.y);
    float ns = di * di;
    float a0 = bv.x + ns * x0.x;
    float a1 = bv.y + ns * x0.y;
    float a2 = bv.z + ns * x1.x;
    float a3 = bv.w + ns * x1.y;
    int s = ptr[i], e = ptr[i + 1];
    for (int k = s; k < e; k++) {
        int r = srcs[k];
        float w = di * dinv[r];
        uint2 v = *(const uint2*)&xw[(size_t)r * cDw + w0];
        float2 v0 = unpack_bf16(v.x), v1 = unpack_bf16(v.y);
        a0 += w * v0.x; a1 += w * v0.y; a2 += w * v1.x; a3 += w * v1.y;
    }
    out[(size_t)i * cDw + w0] = pack_bf16(tanhf(a0), tanhf(a1));
    out[(size_t)i * cDw + w0 + 1] = pack_bf16(tanhf(a2), tanhf(a3));
}

// ---------------- tensor-core pair attention (packed bf16 I/O) ----------------
constexpr int ATT_SMEM_W = 128 * 68 + 64 * 68 + 256;
constexpr int ATT_SMEM = ATT_SMEM_W * 4;

__global__ __launch_bounds__(256) void attn_tc(const uint32_t* __restrict__ qkv,
                                               uint32_t* __restrict__ out) {
    extern __shared__ __align__(16) uint32_t sm[];
    uint32_t(*Qs)[36] = (uint32_t(*)[36])sm;
    uint32_t(*Ks)[36] = (uint32_t(*)[36])(sm + 128 * 36);
    uint32_t(*P)[68] = (uint32_t(*)[68])sm;
    uint32_t(*Vs)[68] = (uint32_t(*)[68])(sm + 128 * 68);
    float* stats = (float*)(sm + 128 * 68 + 64 * 68);  // [2][128]

    const uint32_t* Q = qkv;
    const uint32_t* Kx = qkv + (size_t)cN * cDw;
    const uint32_t* V = qkv + 2 * (size_t)cN * cDw;

    int p = blockIdx.x >> 1, half = blockIdx.x & 1;
    int q0 = p * 256 + half * 128;
    int k0 = p * 256 + (half ^ 1) * 128;

    int tid = threadIdx.x;
    int lane = tid & 31, warp = tid >> 5;
    int wm = warp & 3, wn = warp >> 2;
    int g = lane >> 2, q4 = lane & 3;

    int a_ro = ((lane >> 3) & 1) * 8 + (lane & 7);
    int a_co = (lane >> 4) * 4;
    int b_ro = ((lane >> 4) << 3) + (lane & 7);
    int b_co = ((lane >> 3) & 1) * 4;

    // ---- phase 1: S = Q K^T (128x128) over 8 chunks of 64 dims ----
    float acc[2][8][4] = {};
    int srow = tid >> 1, sw0 = (tid & 1) * 16;
    for (int dc = 0; dc < 8; dc++) {
        {
            const uint32_t* qp = &Q[(size_t)(q0 + srow) * cDw + dc * 32 + sw0];
            const uint32_t* kp = &Kx[(size_t)(k0 + srow) * cDw + dc * 32 + sw0];
#pragma unroll
            for (int i = 0; i < 4; i++) {
                *(uint4*)&Qs[srow][sw0 + 4 * i] = *(const uint4*)&qp[4 * i];
                *(uint4*)&Ks[srow][sw0 + 4 * i] = *(const uint4*)&kp[4 * i];
            }
        }
        __syncthreads();
#pragma unroll
        for (int c = 0; c < 4; c++) {
            uint32_t af[2][4];
            ldsm4(af[0], &Qs[wm * 32 + a_ro][c * 8 + a_co]);
            ldsm4(af[1], &Qs[wm * 32 + 16 + a_ro][c * 8 + a_co]);
            uint32_t bf[8][2];
#pragma unroll
            for (int nt2 = 0; nt2 < 4; nt2++) {
                uint32_t r[4];
                ldsm4(r, &Ks[wn * 64 + nt2 * 16 + b_ro][c * 8 + b_co]);
                bf[2 * nt2][0] = r[0]; bf[2 * nt2][1] = r[1];
                bf[2 * nt2 + 1][0] = r[2]; bf[2 * nt2 + 1][1] = r[3];
            }
#pragma unroll
            for (int mt = 0; mt < 2; mt++)
#pragma unroll
                for (int nt = 0; nt < 8; nt++) mma_bf16(acc[mt][nt], af[mt], bf[nt]);
        }
        __syncthreads();
    }

    // ---- phase 2: softmax ----
    constexpr float scale = 0.0441941738241592f;  // 1/sqrt(512)
#pragma unroll
    for (int mt = 0; mt < 2; mt++)
#pragma unroll
        for (int nt = 0; nt < 8; nt++)
#pragma unroll
            for (int j = 0; j < 4; j++) acc[mt][nt][j] *= scale;

    float mx[2][2];
#pragma unroll
    for (int mt = 0; mt < 2; mt++) {
        float m0 = -1e30f, m1 = -1e30f;
#pragma unroll
        for (int nt = 0; nt < 8; nt++) {
            m0 = fmaxf(m0, fmaxf(acc[mt][nt][0], acc[mt][nt][1]));
            m1 = fmaxf(m1, fmaxf(acc[mt][nt][2], acc[mt][nt][3]));
        }
#pragma unroll
        for (int d = 1; d < 4; d <<= 1) {
            m0 = fmaxf(m0, __shfl_xor_sync(0xffffffffu, m0, d));
            m1 = fmaxf(m1, __shfl_xor_sync(0xffffffffu, m1, d));
        }
        mx[mt][0] = m0; mx[mt][1] = m1;
    }
    if (q4 == 0) {
#pragma unroll
        for (int mt = 0; mt < 2; mt++) {
            int r = wm * 32 + mt * 16 + g;
            stats[wn * 128 + r] = mx[mt][0];
            stats[wn * 128 + r + 8] = mx[mt][1];
        }
    }
    __syncthreads();
    float rmax[2][2], rsum[2][2];
#pragma unroll
    for (int mt = 0; mt < 2; mt++) {
        int r = wm * 32 + mt * 16 + g;
        rmax[mt][0] = fmaxf(stats[r], stats[128 + r]);
        rmax[mt][1] = fmaxf(stats[r + 8], stats[128 + r + 8]);
    }
#pragma unroll
    for (int mt = 0; mt < 2; mt++) {
        float s0 = 0.f, s1 = 0.f;
#pragma unroll
        for (int nt = 0; nt < 8; nt++) {
            acc[mt][nt][0] = __expf(acc[mt][nt][0] - rmax[mt][0]);
            acc[mt][nt][1] = __expf(acc[mt][nt][1] - rmax[mt][0]);
            acc[mt][nt][2] = __expf(acc[mt][nt][2] - rmax[mt][1]);
            acc[mt][nt][3] = __expf(acc[mt][nt][3] - rmax[mt][1]);
            s0 += acc[mt][nt][0] + acc[mt][nt][1];
            s1 += acc[mt][nt][2] + acc[mt][nt][3];
        }
#pragma unroll
        for (int d = 1; d < 4; d <<= 1) {
            s0 += __shfl_xor_sync(0xffffffffu, s0, d);
            s1 += __shfl_xor_sync(0xffffffffu, s1, d);
        }
        rsum[mt][0] = s0; rsum[mt][1] = s1;
    }
    __syncthreads();
    if (q4 == 0) {
#pragma unroll
        for (int mt = 0; mt < 2; mt++) {
            int r = wm * 32 + mt * 16 + g;
            stats[wn * 128 + r] = rsum[mt][0];
            stats[wn * 128 + r + 8] = rsum[mt][1];
        }
    }
    __syncthreads();
#pragma unroll
    for (int mt = 0; mt < 2; mt++) {
        int r = wm * 32 + mt * 16 + g;
        float i0 = 1.0f / (stats[r] + stats[128 + r]);
        float i1 = 1.0f / (stats[r + 8] + stats[128 + r + 8]);
#pragma unroll
        for (int nt = 0; nt < 8; nt++) {
            int kp = wn * 32 + nt * 4 + q4;
            P[r][kp] = pack_bf16(acc[mt][nt][0] * i0, acc[mt][nt][1] * i0);
            P[r + 8][kp] = pack_bf16(acc[mt][nt][2] * i1, acc[mt][nt][3] * i1);
        }
    }
    __syncthreads();

    // ---- phase 3: O = P V ----
    int vkp = tid >> 2, vd0 = (tid & 3) * 16;
    for (int nc = 0; nc < 8; nc++) {
        {
            const uint32_t* v0 = &V[(size_t)(k0 + 2 * vkp) * cDw + nc * 32 + (tid & 3) * 8];
            const uint32_t* v1 = v0 + cDw;
#pragma unroll
            for (int j = 0; j < 8; j++) {
                uint32_t a = v0[j], b = v1[j];
                Vs[vd0 + 2 * j][vkp] = __byte_perm(a, b, 0x5410);
                Vs[vd0 + 2 * j + 1][vkp] = __byte_perm(a, b, 0x7632);
            }
        }
        __syncthreads();
        float o[2][4][4] = {};
#pragma unroll
        for (int c = 0; c < 8; c++) {
            uint32_t af[2][4];
            ldsm4(af[0], &P[wm * 32 + a_ro][c * 8 + a_co]);
            ldsm4(af[1], &P[wm * 32 + 16 + a_ro][c * 8 + a_co]);
            uint32_t bf[4][2];
#pragma unroll
            for (int nt2 = 0; nt2 < 2; nt2++) {
                uint32_t r[4];
                ldsm4(r, &Vs[wn * 32 + nt2 * 16 + b_ro][c * 8 + b_co]);
                bf[2 * nt2][0] = r[0]; bf[2 * nt2][1] = r[1];
                bf[2 * nt2 + 1][0] = r[2]; bf[2 * nt2 + 1][1] = r[3];
            }
#pragma unroll
            for (int mt = 0; mt < 2; mt++)
#pragma unroll
                for (int nt = 0; nt < 4; nt++) mma_bf16(o[mt][nt], af[mt], bf[nt]);
        }
#pragma unroll
        for (int mt = 0; mt < 2; mt++)
#pragma unroll
            for (int nt = 0; nt < 4; nt++) {
                int r = q0 + wm * 32 + mt * 16 + g;
                int widx = nc * 32 + wn * 16 + nt * 4 + q4;
                out[(size_t)r * cDw + widx] = pack_bf16(o[mt][nt][0], o[mt][nt][1]);
                out[(size_t)(r + 8) * cDw + widx] = pack_bf16(o[mt][nt][2], o[mt][nt][3]);
            }
        __syncthreads();
    }
}

// ---------------- fc2 (tanh) -> fc3 -> per-doc mean-pool sums ----------------
__global__ __launch_bounds__(256) void fc2pool(
    const float* __restrict__ h, const float* __restrict__ w2,
    const float* __restrict__ b2, const float* __restrict__ w3,
    const float* __restrict__ b3, float* __restrict__ util) {
    int lane = threadIdx.x & 31, wy = threadIdx.x >> 5;
    int r = blockIdx.x * 8 + wy;
    const float* hr = h + (size_t)r * cD;
    float a = b2[lane];
#pragma unroll 4
    for (int k = 0; k < cD; k += 4) {
        float4 hv = *(const float4*)&hr[k];
        a += hv.x * w2[(k + 0) * 32 + lane];
        a += hv.y * w2[(k + 1) * 32 + lane];
        a += hv.z * w2[(k + 2) * 32 + lane];
        a += hv.w * w2[(k + 3) * 32 + lane];
    }
    a = tanhf(a);
    float pc = a * w3[lane];
#pragma unroll
    for (int off = 16; off; off >>= 1) pc += __shfl_xor_sync(0xffffffffu, pc, off);
    if (lane == 0) atomicAdd(&util[r >> 7], pc + b3[0]);
}

__global__ void zero_f_kernel(float* p, int n) {
    int i = blockIdx.x * blockDim.x + threadIdx.x;
    if (i < n) p[i] = 0.0f;
}

__global__ void final_kernel(const float* __restrict__ util, const int* __restrict__ ia,
                             const int* __restrict__ ib, float* __restrict__ out) {
    int p = threadIdx.x;
    if (p < 32) {
        float d = (util[ib[p]] - util[ia[p]]) * (1.0f / 128.0f);
        out[p] = 1.0f / (1.0f + __expf(-d));
    }
}

// ---------------- launch orchestration ---------------------------------------
extern "C" void kernel_launch(void* const* d_in, const int* in_sizes, int n_in,
                              void* d_out, int out_size) {
    const float* x      = (const float*)d_in[0];
    const float* b_in   = (const float*)d_in[2];
    const float* b_mid  = (const float*)d_in[4];
    const float* b_out  = (const float*)d_in[6];
    const float* fc1_b  = (const float*)d_in[8];
    const float* fc2_w  = (const float*)d_in[9];
    const float* fc2_b  = (const float*)d_in[10];
    const float* fc3_w  = (const float*)d_in[11];
    const float* fc3_b  = (const float*)d_in[12];
    const float* qkv1_b = (const float*)d_in[14];
    const float* qkv2_b = (const float*)d_in[16];
    const float* qkv3_b = (const float*)d_in[18];
    const int* ei       = (const int*)d_in[19];
    const int* idx_a    = (const int*)d_in[22];
    const int* idx_b    = (const int*)d_in[23];

    float* F;
    int* I;
    uint32_t* Wb;
    uint32_t* U;
    cudaGetSymbolAddress((void**)&F, g_f);
    cudaGetSymbolAddress((void**)&I, g_i);
    cudaGetSymbolAddress((void**)&Wb, g_w);
    cudaGetSymbolAddress((void**)&U, g_u);

    cudaFuncSetAttribute(attn_tc, cudaFuncAttributeMaxDynamicSharedMemorySize, ATT_SMEM);
    cudaFuncSetAttribute(gemm_wm<0, 1>, cudaFuncAttributeMaxDynamicSharedMemorySize, GEMM_DYN);
    cudaFuncSetAttribute(gemm_wm<1, 1>, cudaFuncAttributeMaxDynamicSharedMemorySize, GEMM_DYN);
    cudaFuncSetAttribute(gemm_wm<2, 0>, cudaFuncAttributeMaxDynamicSharedMemorySize, GEMM_DYN);

    uint32_t* XP   = U + UP_XP;
    uint32_t* HP   = U + UP_H;
    uint32_t* XWP  = U + UP_XW;
    uint32_t* HAP  = U + UP_HA;
    uint32_t* T1P  = U + UP_T1;
    uint32_t* T2P  = U + UP_T2;
    uint32_t* QKVP = U + UP_QKV;
    float* HAF  = F + OFF_HAF;
    float* DINV = F + OFF_DINV;
    float* UTIL = F + OFF_UTIL;

    // ---- prep: exactly 5 launches so ncu -s 5 profiles the first GEMM ----
    pack_all_kernel<<<(int)((PACK_TOT + 255) / 256), 256>>>(
        x, (const float*)d_in[1], (const float*)d_in[3], (const float*)d_in[5],
        (const float*)d_in[7], (const float*)d_in[13], (const float*)d_in[15],
        (const float*)d_in[17], XP, Wb);
    zero_int_kernel<<<(2 * cN + 255) / 256, 256>>>(I + ICNT, 2 * cN);
    count_edges_kernel<<<cE / 256, 256>>>(ei, I + ICNT);
    scan_dinv_kernel<<<1, 256>>>(I + ICNT, I + IPTR, DINV);
    fill_csr_kernel<<<cE / 256, 256>>>(ei, I + IPTR, I + ICUR, I + ISRC);

    const uint32_t* winp[4] = {Wb + PW_IN, Wb + PW_MID, Wb + PW_MID, Wb + PW_OUT};
    const float*    bin[4]  = {b_in, b_mid, b_mid, b_out};

    for (int layer = 0; layer < 4; layer++) {
        const uint32_t* hin = (layer == 0) ? XP : HP;
        int Kp2 = (layer == 0) ? cFw : cDw;
        gemm_wm<0, 1><<<dim3(cD / 128, cN / 128, 1), 256, GEMM_DYN>>>(
            hin, winp[layer], nullptr, XWP, Kp2, cD, 0, 0, 0, 0);
        gcn_agg_tanh<<<cN, 128>>>(XWP, bin[layer], I + IPTR, I + ISRC, DINV, HAP);
        gemm_wm<1, 1><<<dim3(cH / 128, cN / 128, 3), 256, GEMM_DYN>>>(
            HAP, Wb + PW_Q1, qkv1_b, T1P, cDw, cH,
            0, (size_t)cH * cDw, cH, (size_t)cN * cHw);
        gemm_wm<1, 1><<<dim3(cH / 128, cN / 128, 3), 256, GEMM_DYN>>>(
            T1P, Wb + PW_Q2, qkv2_b, T2P, cHw, cH,
            (size_t)cN * cHw, (size_t)cH * cHw, cH, (size_t)cN * cHw);
        gemm_wm<1, 1><<<dim3(cD / 128, cN / 128, 3), 256, GEMM_DYN>>>(
            T2P, Wb + PW_Q3, qkv3_b, QKVP, cHw, cD,
            (size_t)cN * cHw, (size_t)cD * cHw, cD, (size_t)cN * cDw);
        attn_tc<<<64, 256, ATT_SMEM>>>(QKVP, HP);
    }

    // ---- head ----
    gemm_wm<2, 0><<<dim3(cD / 128, cN / 128, 1), 256, GEMM_DYN>>>(
        HP, Wb + PW_FC1, fc1_b, HAF, cDw, cD, 0, 0, 0, 0);
    zero_f_kernel<<<1, 64>>>(UTIL, 64);
    fc2pool<<<cN / 8, 256>>>(HAF, fc2_w, fc2_b, fc3_w, fc3_b, UTIL);
    final_kernel<<<1, 32>>>(UTIL, idx_a, idx_b, (float*)d_out);
}

// round 7
// speedup vs baseline: 1.9575x; 1.0120x over previous
#include <cuda_runtime.h>
#include <cuda_bf16.h>
#include <cstdint>
#include <math.h>

// Problem constants (fixed by the dataset instance)
constexpr int cN = 8192;    // nodes
constexpr int cD = 512;     // model units
constexpr int cH = 1024;    // hidden units
constexpr int cE = 131072;  // edges
constexpr int cF = 128;     // input features

constexpr int cDw = cD / 2;  // 256 packed words per row
constexpr int cHw = cH / 2;  // 512
constexpr int cFw = cF / 2;  // 64

// ---------------- scratch (device globals; no allocation allowed) ------------
constexpr size_t UP_XP   = 0;
constexpr size_t UP_H    = UP_XP  + (size_t)cN * cFw;
constexpr size_t UP_XW   = UP_H   + (size_t)cN * cDw;
constexpr size_t UP_HA   = UP_XW  + (size_t)cN * cDw;
constexpr size_t UP_T1   = UP_HA  + (size_t)cN * cDw;
constexpr size_t UP_T2   = UP_T1  + 3ull * cN * cHw;
constexpr size_t UP_QKV  = UP_T2  + 3ull * cN * cHw;
constexpr size_t TOTU    = UP_QKV + 3ull * cN * cDw;

__device__ __align__(16) uint32_t g_u[TOTU];

constexpr size_t OFF_HAF  = 0;
constexpr size_t OFF_DINV = OFF_HAF + (size_t)cN * cD;
constexpr size_t OFF_UTIL = OFF_DINV + cN;
constexpr size_t TOTF     = OFF_UTIL + 64;

__device__ __align__(16) float g_f[TOTF];

constexpr int ICNT = 0;
constexpr int ICUR = cN;
constexpr int IPTR = 2 * cN;
constexpr int ISRC = 3 * cN + 1;
constexpr int TOTI = 3 * cN + 1 + cE;

__device__ int g_i[TOTI];

// Packed bf16-pair weights: layout [z][N][K/2] uint32 (n-major, K-pairs)
constexpr size_t PW_IN  = 0;
constexpr size_t PW_MID = PW_IN  + (size_t)cF * cD / 2;
constexpr size_t PW_OUT = PW_MID + (size_t)cD * cD / 2;
constexpr size_t PW_FC1 = PW_OUT + (size_t)cD * cD / 2;
constexpr size_t PW_Q1  = PW_FC1 + (size_t)cD * cD / 2;
constexpr size_t PW_Q2  = PW_Q1  + 3ull * cD * cH / 2;
constexpr size_t PW_Q3  = PW_Q2  + 3ull * cH * cH / 2;
constexpr size_t TOTW   = PW_Q3  + 3ull * cH * cD / 2;

__device__ __align__(16) uint32_t g_w[TOTW];

// ---------------- small helpers ----------------------------------------------
__device__ __forceinline__ uint32_t pack_bf16(float lo, float hi) {
    __nv_bfloat162 v = __floats2bfloat162_rn(lo, hi);
    return *(uint32_t*)&v;
}

__device__ __forceinline__ float2 unpack_bf16(uint32_t u) {
    return __bfloat1622float2(*(__nv_bfloat162*)&u);
}

__device__ __forceinline__ void mma_bf16(float (&c)[4], const uint32_t (&a)[4],
                                         const uint32_t (&b)[2]) {
    asm volatile(
        "mma.sync.aligned.m16n8k16.row.col.f32.bf16.bf16.f32 "
        "{%0,%1,%2,%3},{%4,%5,%6,%7},{%8,%9},{%0,%1,%2,%3};"
        : "+f"(c[0]), "+f"(c[1]), "+f"(c[2]), "+f"(c[3])
        : "r"(a[0]), "r"(a[1]), "r"(a[2]), "r"(a[3]), "r"(b[0]), "r"(b[1]));
}

__device__ __forceinline__ void ldsm4(uint32_t (&r)[4], const uint32_t* p) {
    uint32_t a = (uint32_t)__cvta_generic_to_shared(p);
    asm volatile("ldmatrix.sync.aligned.m8n8.x4.shared.b16 {%0,%1,%2,%3}, [%4];"
                 : "=r"(r[0]), "=r"(r[1]), "=r"(r[2]), "=r"(r[3]) : "r"(a));
}

__device__ __forceinline__ void cp_async16(const void* smem_dst, const void* gsrc) {
    uint32_t d = (uint32_t)__cvta_generic_to_shared(smem_dst);
    asm volatile("cp.async.cg.shared.global [%0], [%1], 16;" :: "r"(d), "l"(gsrc)
                 : "memory");
}
#define CP_COMMIT() asm volatile("cp.async.commit_group;" ::: "memory")
#define CP_WAIT(n)  asm volatile("cp.async.wait_group %0;" :: "n"(n) : "memory")

// ---------------- utility kernels --------------------------------------------
__global__ void zero_int_kernel(int* p, int n) {
    int i = blockIdx.x * blockDim.x + threadIdx.x;
    if (i < n) p[i] = 0;
}

constexpr int XPn = cN * cFw;
constexpr size_t PACK_TOT = (size_t)XPn + TOTW;

// One kernel: pack x + all weights into bf16-pair layouts.
__global__ void pack_all_kernel(const float* __restrict__ x,
                                const float* __restrict__ w_in,
                                const float* __restrict__ w_mid,
                                const float* __restrict__ w_out,
                                const float* __restrict__ fc1_w,
                                const float* __restrict__ q1,
                                const float* __restrict__ q2,
                                const float* __restrict__ q3,
                                uint32_t* __restrict__ XP,
                                uint32_t* __restrict__ Wb) {
    size_t i = (size_t)blockIdx.x * blockDim.x + threadIdx.x;
    if (i >= PACK_TOT) return;
    if (i < (size_t)XPn) {
        XP[i] = pack_bf16(x[2 * i], x[2 * i + 1]);
        return;
    }
    size_t j = i - XPn;
    const float* W;
    size_t lo;
    int K, N;
    if (j < PW_MID)      { W = w_in;  lo = PW_IN;  K = cF; N = cD; }
    else if (j < PW_OUT) { W = w_mid; lo = PW_MID; K = cD; N = cD; }
    else if (j < PW_FC1) { W = w_out; lo = PW_OUT; K = cD; N = cD; }
    else if (j < PW_Q1)  { W = fc1_w; lo = PW_FC1; K = cD; N = cD; }
    else if (j < PW_Q2)  { W = q1;    lo = PW_Q1;  K = cD; N = cH; }
    else if (j < PW_Q3)  { W = q2;    lo = PW_Q2;  K = cH; N = cH; }
    else                 { W = q3;    lo = PW_Q3;  K = cH; N = cD; }
    size_t l = j - lo;
    int kp2 = K >> 1;
    int z = (int)(l / ((size_t)N * kp2));
    int rem = (int)(l - (size_t)z * N * kp2);
    int n = rem / kp2;
    int kp = rem - n * kp2;
    const float* Wz = W + (size_t)z * K * N;
    Wb[j] = pack_bf16(Wz[(size_t)(2 * kp) * N + n], Wz[(size_t)(2 * kp + 1) * N + n]);
}

__global__ void count_edges_kernel(const int* __restrict__ ei, int* __restrict__ cnt) {
    int e = blockIdx.x * blockDim.x + threadIdx.x;
    if (e < cE) atomicAdd(&cnt[ei[cE + e]], 1);
}

__global__ void scan_dinv_kernel(const int* __restrict__ cnt, int* __restrict__ ptr,
                                 float* __restrict__ dinv) {
    __shared__ int part[257];
    int t = threadIdx.x;
    int base = t * 32;
    int s = 0;
    for (int i = 0; i < 32; i++) s += cnt[base + i];
    part[t] = s;
    __syncthreads();
    if (t == 0) {
        int run = 0;
        for (int i = 0; i < 256; i++) { int v = part[i]; part[i] = run; run += v; }
        part[256] = run;
    }
    __syncthreads();
    int run = part[t];
    for (int i = 0; i < 32; i++) {
        int c = cnt[base + i];
        ptr[base + i] = run;
        run += c;
        dinv[base + i] = rsqrtf((float)c + 1.0f);
    }
    if (t == 0) ptr[cN] = part[256];
}

__global__ void fill_csr_kernel(const int* __restrict__ ei, const int* __restrict__ ptr,
                                int* __restrict__ cur, int* __restrict__ srcs) {
    int e = blockIdx.x * blockDim.x + threadIdx.x;
    if (e < cE) {
        int d = ei[cE + e];
        int p = atomicAdd(&cur[d], 1);
        srcs[ptr[d] + p] = ei[e];
    }
}

// ---------------- warp-MMA bf16 GEMM (3-stage cp.async, BK=64) ----------------
// C(M x N) = act(A @ W + bias). A: packed bf16 [M][K/2]; Wp: [z][N][K/2].
// Tile 128x128, BK=64 (32 words), 256 threads (8 warps 4x2, warp tile 32x64).
// One __syncthreads per K-step; staging issued 2 steps ahead.
// ACT: 0=none 1=relu 2=tanh.  OUTF: 0=fp32, 1=packed bf16.
constexpr int GEMM_DYN = 3 * 2 * 128 * 36 * 4;  // 110592 bytes

template <int ACT, int OUTF>
__global__ __launch_bounds__(256) void gemm_wm(
    const uint32_t* __restrict__ Ap, const uint32_t* __restrict__ Wp,
    const float* __restrict__ bias, void* __restrict__ Cout,
    int Kp2, int N, size_t sA, size_t sW, size_t sB, size_t sC) {
    extern __shared__ __align__(16) uint32_t sh[];
    uint32_t(*As)[128][36] = (uint32_t(*)[128][36])sh;
    uint32_t(*Bs)[128][36] = (uint32_t(*)[128][36])(sh + 3 * 128 * 36);

    int z = blockIdx.z;
    Ap += z * sA;
    Wp += z * sW;
    const float* bz = bias ? bias + z * sB : nullptr;

    int tid = threadIdx.x;
    int lane = tid & 31, warp = tid >> 5;
    int wm = warp & 3, wn = warp >> 2;  // 4 x 2 warp grid
    int g = lane >> 2, q4 = lane & 3;

    int rowB = blockIdx.y * 128;
    int colB = blockIdx.x * 128;

    // ldmatrix lane offsets
    int a_ro = ((lane >> 3) & 1) * 8 + (lane & 7);
    int a_co = (lane >> 4) * 4;
    int b_ro = ((lane >> 4) << 3) + (lane & 7);
    int b_co = ((lane >> 3) & 1) * 4;

    // staging: 128 rows x 32 words per tile; thread -> row tid>>1, words (tid&1)*16
    int srow = tid >> 1, sw0 = (tid & 1) * 16;

    auto stage = [&](int buf, int kt) {
        const uint32_t* as = &Ap[(size_t)(rowB + srow) * Kp2 + kt * 32 + sw0];
        const uint32_t* bs = &Wp[(size_t)(colB + srow) * Kp2 + kt * 32 + sw0];
#pragma unroll
        for (int i = 0; i < 4; i++) {
            cp_async16(&As[buf][srow][sw0 + 4 * i], as + 4 * i);
            cp_async16(&Bs[buf][srow][sw0 + 4 * i], bs + 4 * i);
        }
        CP_COMMIT();
    };

    float acc[2][8][4] = {};

    int KT = Kp2 >> 5;  // number of BK=64 steps (always >= 2 here)
    stage(0, 0);
    stage(1, 1);

    for (int kt = 0; kt < KT; kt++) {
        int cur = kt % 3;
        if (kt + 1 < KT) CP_WAIT(1);
        else             CP_WAIT(0);
        __syncthreads();
        if (kt + 2 < KT) stage((kt + 2) % 3, kt + 2);
#pragma unroll
        for (int c = 0; c < 4; c++) {  // four k16 chunks per BK=64
            uint32_t af[2][4];
            ldsm4(af[0], &As[cur][wm * 32 + a_ro][c * 8 + a_co]);
            ldsm4(af[1], &As[cur][wm * 32 + 16 + a_ro][c * 8 + a_co]);
            uint32_t bf[8][2];
#pragma unroll
            for (int nt2 = 0; nt2 < 4; nt2++) {
                uint32_t r[4];
                ldsm4(r, &Bs[cur][wn * 64 + nt2 * 16 + b_ro][c * 8 + b_co]);
                bf[2 * nt2][0] = r[0]; bf[2 * nt2][1] = r[1];
                bf[2 * nt2 + 1][0] = r[2]; bf[2 * nt2 + 1][1] = r[3];
            }
#pragma unroll
            for (int mt = 0; mt < 2; mt++)
#pragma unroll
                for (int nt = 0; nt < 8; nt++) mma_bf16(acc[mt][nt], af[mt], bf[nt]);
        }
    }

    // epilogue
#pragma unroll
    for (int mt = 0; mt < 2; mt++) {
#pragma unroll
        for (int nt = 0; nt < 8; nt++) {
            int r0 = rowB + wm * 32 + mt * 16 + g;
            int c = colB + wn * 64 + nt * 8 + q4 * 2;
            float v00 = acc[mt][nt][0], v01 = acc[mt][nt][1];
            float v10 = acc[mt][nt][2], v11 = acc[mt][nt][3];
            if (bz) {
                float b0 = bz[c], b1 = bz[c + 1];
                v00 += b0; v01 += b1; v10 += b0; v11 += b1;
            }
            if (ACT == 1) {
                v00 = fmaxf(v00, 0.f); v01 = fmaxf(v01, 0.f);
                v10 = fmaxf(v10, 0.f); v11 = fmaxf(v11, 0.f);
            } else if (ACT == 2) {
                v00 = tanhf(v00); v01 = tanhf(v01);
                v10 = tanhf(v10); v11 = tanhf(v11);
            }
            if (OUTF == 1) {
                uint32_t* Cw = (uint32_t*)Cout + z * sC;
                Cw[(size_t)r0 * (N >> 1) + (c >> 1)] = pack_bf16(v00, v01);
                Cw[(size_t)(r0 + 8) * (N >> 1) + (c >> 1)] = pack_bf16(v10, v11);
            } else {
                float* Cf = (float*)Cout + z * sC;
                float2 p0 = {v00, v01};
                float2 p1 = {v10, v11};
                *(float2*)&Cf[(size_t)r0 * N + c] = p0;
                *(float2*)&Cf[(size_t)(r0 + 8) * N + c] = p1;
            }
        }
    }
}

// ---------------- GCN aggregation (packed bf16 in/out) ------------------------
__global__ __launch_bounds__(128) void gcn_agg_tanh(
    const uint32_t* __restrict__ xw, const float* __restrict__ bias,
    const int* __restrict__ ptr, const int* __restrict__ srcs,
    const float* __restrict__ dinv, uint32_t* __restrict__ out) {
    int i = blockIdx.x;
    int w0 = threadIdx.x * 2;
    float di = dinv[i];
    float4 bv = *(const float4*)&bias[w0 * 2];
    uint2 xv = *(const uint2*)&xw[(size_t)i * cDw + w0];
    float2 x0 = unpack_bf16(xv.x), x1 = unpack_bf16(xv.y);
    float ns = di * di;
    float a0 = bv.x + ns * x0.x;
    float a1 = bv.y + ns * x0.y;
    float a2 = bv.z + ns * x1.x;
    float a3 = bv.w + ns * x1.y;
    int s = ptr[i], e = ptr[i + 1];
    for (int k = s; k < e; k++) {
        int r = srcs[k];
        float w = di * dinv[r];
        uint2 v = *(const uint2*)&xw[(size_t)r * cDw + w0];
        float2 v0 = unpack_bf16(v.x), v1 = unpack_bf16(v.y);
        a0 += w * v0.x; a1 += w * v0.y; a2 += w * v1.x; a3 += w * v1.y;
    }
    out[(size_t)i * cDw + w0] = pack_bf16(tanhf(a0), tanhf(a1));
    out[(size_t)i * cDw + w0 + 1] = pack_bf16(tanhf(a2), tanhf(a3));
}

// ---------------- tensor-core pair attention (packed bf16 I/O) ----------------
constexpr int ATT_SMEM_W = 128 * 68 + 64 * 68 + 256;
constexpr int ATT_SMEM = ATT_SMEM_W * 4;

__global__ __launch_bounds__(256) void attn_tc(const uint32_t* __restrict__ qkv,
                                               uint32_t* __restrict__ out) {
    extern __shared__ __align__(16) uint32_t sm[];
    uint32_t(*Qs)[36] = (uint32_t(*)[36])sm;
    uint32_t(*Ks)[36] = (uint32_t(*)[36])(sm + 128 * 36);
    uint32_t(*P)[68] = (uint32_t(*)[68])sm;
    uint32_t(*Vs)[68] = (uint32_t(*)[68])(sm + 128 * 68);
    float* stats = (float*)(sm + 128 * 68 + 64 * 68);  // [2][128]

    const uint32_t* Q = qkv;
    const uint32_t* Kx = qkv + (size_t)cN * cDw;
    const uint32_t* V = qkv + 2 * (size_t)cN * cDw;

    int p = blockIdx.x >> 1, half = blockIdx.x & 1;
    int q0 = p * 256 + half * 128;
    int k0 = p * 256 + (half ^ 1) * 128;

    int tid = threadIdx.x;
    int lane = tid & 31, warp = tid >> 5;
    int wm = warp & 3, wn = warp >> 2;
    int g = lane >> 2, q4 = lane & 3;

    int a_ro = ((lane >> 3) & 1) * 8 + (lane & 7);
    int a_co = (lane >> 4) * 4;
    int b_ro = ((lane >> 4) << 3) + (lane & 7);
    int b_co = ((lane >> 3) & 1) * 4;

    // ---- phase 1: S = Q K^T (128x128) over 8 chunks of 64 dims ----
    float acc[2][8][4] = {};
    int srow = tid >> 1, sw0 = (tid & 1) * 16;
    for (int dc = 0; dc < 8; dc++) {
        {
            const uint32_t* qp = &Q[(size_t)(q0 + srow) * cDw + dc * 32 + sw0];
            const uint32_t* kp = &Kx[(size_t)(k0 + srow) * cDw + dc * 32 + sw0];
#pragma unroll
            for (int i = 0; i < 4; i++) {
                *(uint4*)&Qs[srow][sw0 + 4 * i] = *(const uint4*)&qp[4 * i];
                *(uint4*)&Ks[srow][sw0 + 4 * i] = *(const uint4*)&kp[4 * i];
            }
        }
        __syncthreads();
#pragma unroll
        for (int c = 0; c < 4; c++) {
            uint32_t af[2][4];
            ldsm4(af[0], &Qs[wm * 32 + a_ro][c * 8 + a_co]);
            ldsm4(af[1], &Qs[wm * 32 + 16 + a_ro][c * 8 + a_co]);
            uint32_t bf[8][2];
#pragma unroll
            for (int nt2 = 0; nt2 < 4; nt2++) {
                uint32_t r[4];
                ldsm4(r, &Ks[wn * 64 + nt2 * 16 + b_ro][c * 8 + b_co]);
                bf[2 * nt2][0] = r[0]; bf[2 * nt2][1] = r[1];
                bf[2 * nt2 + 1][0] = r[2]; bf[2 * nt2 + 1][1] = r[3];
            }
#pragma unroll
            for (int mt = 0; mt < 2; mt++)
#pragma unroll
                for (int nt = 0; nt < 8; nt++) mma_bf16(acc[mt][nt], af[mt], bf[nt]);
        }
        __syncthreads();
    }

    // ---- phase 2: softmax ----
    constexpr float scale = 0.0441941738241592f;  // 1/sqrt(512)
#pragma unroll
    for (int mt = 0; mt < 2; mt++)
#pragma unroll
        for (int nt = 0; nt < 8; nt++)
#pragma unroll
            for (int j = 0; j < 4; j++) acc[mt][nt][j] *= scale;

    float mx[2][2];
#pragma unroll
    for (int mt = 0; mt < 2; mt++) {
        float m0 = -1e30f, m1 = -1e30f;
#pragma unroll
        for (int nt = 0; nt < 8; nt++) {
            m0 = fmaxf(m0, fmaxf(acc[mt][nt][0], acc[mt][nt][1]));
            m1 = fmaxf(m1, fmaxf(acc[mt][nt][2], acc[mt][nt][3]));
        }
#pragma unroll
        for (int d = 1; d < 4; d <<= 1) {
            m0 = fmaxf(m0, __shfl_xor_sync(0xffffffffu, m0, d));
            m1 = fmaxf(m1, __shfl_xor_sync(0xffffffffu, m1, d));
        }
        mx[mt][0] = m0; mx[mt][1] = m1;
    }
    if (q4 == 0) {
#pragma unroll
        for (int mt = 0; mt < 2; mt++) {
            int r = wm * 32 + mt * 16 + g;
            stats[wn * 128 + r] = mx[mt][0];
            stats[wn * 128 + r + 8] = mx[mt][1];
        }
    }
    __syncthreads();
    float rmax[2][2], rsum[2][2];
#pragma unroll
    for (int mt = 0; mt < 2; mt++) {
        int r = wm * 32 + mt * 16 + g;
        rmax[mt][0] = fmaxf(stats[r], stats[128 + r]);
        rmax[mt][1] = fmaxf(stats[r + 8], stats[128 + r + 8]);
    }
#pragma unroll
    for (int mt = 0; mt < 2; mt++) {
        float s0 = 0.f, s1 = 0.f;
#pragma unroll
        for (int nt = 0; nt < 8; nt++) {
            acc[mt][nt][0] = __expf(acc[mt][nt][0] - rmax[mt][0]);
            acc[mt][nt][1] = __expf(acc[mt][nt][1] - rmax[mt][0]);
            acc[mt][nt][2] = __expf(acc[mt][nt][2] - rmax[mt][1]);
            acc[mt][nt][3] = __expf(acc[mt][nt][3] - rmax[mt][1]);
            s0 += acc[mt][nt][0] + acc[mt][nt][1];
            s1 += acc[mt][nt][2] + acc[mt][nt][3];
        }
#pragma unroll
        for (int d = 1; d < 4; d <<= 1) {
            s0 += __shfl_xor_sync(0xffffffffu, s0, d);
            s1 += __shfl_xor_sync(0xffffffffu, s1, d);
        }
        rsum[mt][0] = s0; rsum[mt][1] = s1;
    }
    __syncthreads();
    if (q4 == 0) {
#pragma unroll
        for (int mt = 0; mt < 2; mt++) {
            int r = wm * 32 + mt * 16 + g;
            stats[wn * 128 + r] = rsum[mt][0];
            stats[wn * 128 + r + 8] = rsum[mt][1];
        }
    }
    __syncthreads();
#pragma unroll
    for (int mt = 0; mt < 2; mt++) {
        int r = wm * 32 + mt * 16 + g;
        float i0 = 1.0f / (stats[r] + stats[128 + r]);
        float i1 = 1.0f / (stats[r + 8] + stats[128 + r + 8]);
#pragma unroll
        for (int nt = 0; nt < 8; nt++) {
            int kp = wn * 32 + nt * 4 + q4;
            P[r][kp] = pack_bf16(acc[mt][nt][0] * i0, acc[mt][nt][1] * i0);
            P[r + 8][kp] = pack_bf16(acc[mt][nt][2] * i1, acc[mt][nt][3] * i1);
        }
    }
    __syncthreads();

    // ---- phase 3: O = P V ----
    int vkp = tid >> 2, vd0 = (tid & 3) * 16;
    for (int nc = 0; nc < 8; nc++) {
        {
            const uint32_t* v0 = &V[(size_t)(k0 + 2 * vkp) * cDw + nc * 32 + (tid & 3) * 8];
            const uint32_t* v1 = v0 + cDw;
#pragma unroll
            for (int j = 0; j < 8; j++) {
                uint32_t a = v0[j], b = v1[j];
                Vs[vd0 + 2 * j][vkp] = __byte_perm(a, b, 0x5410);
                Vs[vd0 + 2 * j + 1][vkp] = __byte_perm(a, b, 0x7632);
            }
        }
        __syncthreads();
        float o[2][4][4] = {};
#pragma unroll
        for (int c = 0; c < 8; c++) {
            uint32_t af[2][4];
            ldsm4(af[0], &P[wm * 32 + a_ro][c * 8 + a_co]);
            ldsm4(af[1], &P[wm * 32 + 16 + a_ro][c * 8 + a_co]);
            uint32_t bf[4][2];
#pragma unroll
            for (int nt2 = 0; nt2 < 2; nt2++) {
                uint32_t r[4];
                ldsm4(r, &Vs[wn * 32 + nt2 * 16 + b_ro][c * 8 + b_co]);
                bf[2 * nt2][0] = r[0]; bf[2 * nt2][1] = r[1];
                bf[2 * nt2 + 1][0] = r[2]; bf[2 * nt2 + 1][1] = r[3];
            }
#pragma unroll
            for (int mt = 0; mt < 2; mt++)
#pragma unroll
                for (int nt = 0; nt < 4; nt++) mma_bf16(o[mt][nt], af[mt], bf[nt]);
        }
#pragma unroll
        for (int mt = 0; mt < 2; mt++)
#pragma unroll
            for (int nt = 0; nt < 4; nt++) {
                int r = q0 + wm * 32 + mt * 16 + g;
                int widx = nc * 32 + wn * 16 + nt * 4 + q4;
                out[(size_t)r * cDw + widx] = pack_bf16(o[mt][nt][0], o[mt][nt][1]);
                out[(size_t)(r + 8) * cDw + widx] = pack_bf16(o[mt][nt][2], o[mt][nt][3]);
            }
        __syncthreads();
    }
}

// ---------------- fc2 (tanh) -> fc3 -> per-doc mean-pool sums ----------------
__global__ __launch_bounds__(256) void fc2pool(
    const float* __restrict__ h, const float* __restrict__ w2,
    const float* __restrict__ b2, const float* __restrict__ w3,
    const float* __restrict__ b3, float* __restrict__ util) {
    int lane = threadIdx.x & 31, wy = threadIdx.x >> 5;
    int r = blockIdx.x * 8 + wy;
    const float* hr = h + (size_t)r * cD;
    float a = b2[lane];
#pragma unroll 4
    for (int k = 0; k < cD; k += 4) {
        float4 hv = *(const float4*)&hr[k];
        a += hv.x * w2[(k + 0) * 32 + lane];
        a += hv.y * w2[(k + 1) * 32 + lane];
        a += hv.z * w2[(k + 2) * 32 + lane];
        a += hv.w * w2[(k + 3) * 32 + lane];
    }
    a = tanhf(a);
    float pc = a * w3[lane];
#pragma unroll
    for (int off = 16; off; off >>= 1) pc += __shfl_xor_sync(0xffffffffu, pc, off);
    if (lane == 0) atomicAdd(&util[r >> 7], pc + b3[0]);
}

__global__ void zero_f_kernel(float* p, int n) {
    int i = blockIdx.x * blockDim.x + threadIdx.x;
    if (i < n) p[i] = 0.0f;
}

__global__ void final_kernel(const float* __restrict__ util, const int* __restrict__ ia,
                             const int* __restrict__ ib, float* __restrict__ out) {
    int p = threadIdx.x;
    if (p < 32) {
        float d = (util[ib[p]] - util[ia[p]]) * (1.0f / 128.0f);
        out[p] = 1.0f / (1.0f + __expf(-d));
    }
}

// ---------------- launch orchestration ---------------------------------------
extern "C" void kernel_launch(void* const* d_in, const int* in_sizes, int n_in,
                              void* d_out, int out_size) {
    const float* x      = (const float*)d_in[0];
    const float* b_in   = (const float*)d_in[2];
    const float* b_mid  = (const float*)d_in[4];
    const float* b_out  = (const float*)d_in[6];
    const float* fc1_b  = (const float*)d_in[8];
    const float* fc2_w  = (const float*)d_in[9];
    const float* fc2_b  = (const float*)d_in[10];
    const float* fc3_w  = (const float*)d_in[11];
    const float* fc3_b  = (const float*)d_in[12];
    const float* qkv1_b = (const float*)d_in[14];
    const float* qkv2_b = (const float*)d_in[16];
    const float* qkv3_b = (const float*)d_in[18];
    const int* ei       = (const int*)d_in[19];
    const int* idx_a    = (const int*)d_in[22];
    const int* idx_b    = (const int*)d_in[23];

    float* F;
    int* I;
    uint32_t* Wb;
    uint32_t* U;
    cudaGetSymbolAddress((void**)&F, g_f);
    cudaGetSymbolAddress((void**)&I, g_i);
    cudaGetSymbolAddress((void**)&Wb, g_w);
    cudaGetSymbolAddress((void**)&U, g_u);

    cudaFuncSetAttribute(attn_tc, cudaFuncAttributeMaxDynamicSharedMemorySize, ATT_SMEM);
    cudaFuncSetAttribute(gemm_wm<0, 1>, cudaFuncAttributeMaxDynamicSharedMemorySize, GEMM_DYN);
    cudaFuncSetAttribute(gemm_wm<1, 1>, cudaFuncAttributeMaxDynamicSharedMemorySize, GEMM_DYN);
    cudaFuncSetAttribute(gemm_wm<2, 0>, cudaFuncAttributeMaxDynamicSharedMemorySize, GEMM_DYN);

    uint32_t* XP   = U + UP_XP;
    uint32_t* HP   = U + UP_H;
    uint32_t* XWP  = U + UP_XW;
    uint32_t* HAP  = U + UP_HA;
    uint32_t* T1P  = U + UP_T1;
    uint32_t* T2P  = U + UP_T2;
    uint32_t* QKVP = U + UP_QKV;
    float* HAF  = F + OFF_HAF;
    float* DINV = F + OFF_DINV;
    float* UTIL = F + OFF_UTIL;

    // ---- prep ----
    pack_all_kernel<<<(int)((PACK_TOT + 255) / 256), 256>>>(
        x, (const float*)d_in[1], (const float*)d_in[3], (const float*)d_in[5],
        (const float*)d_in[7], (const float*)d_in[13], (const float*)d_in[15],
        (const float*)d_in[17], XP, Wb);
    zero_int_kernel<<<(2 * cN + 255) / 256, 256>>>(I + ICNT, 2 * cN);
    count_edges_kernel<<<cE / 256, 256>>>(ei, I + ICNT);
    scan_dinv_kernel<<<1, 256>>>(I + ICNT, I + IPTR, DINV);
    fill_csr_kernel<<<cE / 256, 256>>>(ei, I + IPTR, I + ICUR, I + ISRC);

    const uint32_t* winp[4] = {Wb + PW_IN, Wb + PW_MID, Wb + PW_MID, Wb + PW_OUT};
    const float*    bin[4]  = {b_in, b_mid, b_mid, b_out};

    for (int layer = 0; layer < 4; layer++) {
        const uint32_t* hin = (layer == 0) ? XP : HP;
        int Kp2 = (layer == 0) ? cFw : cDw;
        gemm_wm<0, 1><<<dim3(cD / 128, cN / 128, 1), 256, GEMM_DYN>>>(
            hin, winp[layer], nullptr, XWP, Kp2, cD, 0, 0, 0, 0);
        gcn_agg_tanh<<<cN, 128>>>(XWP, bin[layer], I + IPTR, I + ISRC, DINV, HAP);
        gemm_wm<1, 1><<<dim3(cH / 128, cN / 128, 3), 256, GEMM_DYN>>>(
            HAP, Wb + PW_Q1, qkv1_b, T1P, cDw, cH,
            0, (size_t)cH * cDw, cH, (size_t)cN * cHw);
        gemm_wm<1, 1><<<dim3(cH / 128, cN / 128, 3), 256, GEMM_DYN>>>(
            T1P, Wb + PW_Q2, qkv2_b, T2P, cHw, cH,
            (size_t)cN * cHw, (size_t)cH * cHw, cH, (size_t)cN * cHw);
        gemm_wm<1, 1><<<dim3(cD / 128, cN / 128, 3), 256, GEMM_DYN>>>(
            T2P, Wb + PW_Q3, qkv3_b, QKVP, cHw, cD,
            (size_t)cN * cHw, (size_t)cD * cHw, cD, (size_t)cN * cDw);
        attn_tc<<<64, 256, ATT_SMEM>>>(QKVP, HP);
    }

    // ---- head ----
    gemm_wm<2, 0><<<dim3(cD / 128, cN / 128, 1), 256, GEMM_DYN>>>(
        HP, Wb + PW_FC1, fc1_b, HAF, cDw, cD, 0, 0, 0, 0);
    zero_f_kernel<<<1, 64>>>(UTIL, 64);
    fc2pool<<<cN / 8, 256>>>(HAF, fc2_w, fc2_b, fc3_w, fc3_b, UTIL);
    final_kernel<<<1, 32>>>(UTIL, idx_a, idx_b, (float*)d_out);
}

// round 8
// speedup vs baseline: 1.9851x; 1.0141x over previous
#include <cuda_runtime.h>
#include <cuda_bf16.h>
#include <cstdint>
#include <math.h>

// Problem constants (fixed by the dataset instance)
constexpr int cN = 8192;    // nodes
constexpr int cD = 512;     // model units
constexpr int cH = 1024;    // hidden units
constexpr int cE = 131072;  // edges
constexpr int cF = 128;     // input features

constexpr int cDw = cD / 2;  // 256 packed words per row
constexpr int cHw = cH / 2;  // 512
constexpr int cFw = cF / 2;  // 64

// ---------------- scratch (device globals; no allocation allowed) ------------
constexpr size_t UP_XP   = 0;
constexpr size_t UP_H    = UP_XP  + (size_t)cN * cFw;
constexpr size_t UP_XW   = UP_H   + (size_t)cN * cDw;
constexpr size_t UP_HA   = UP_XW  + (size_t)cN * cDw;
constexpr size_t UP_T1   = UP_HA  + (size_t)cN * cDw;
constexpr size_t UP_T2   = UP_T1  + 3ull * cN * cHw;
constexpr size_t UP_QKV  = UP_T2  + 3ull * cN * cHw;
constexpr size_t TOTU    = UP_QKV + 3ull * cN * cDw;

__device__ __align__(16) uint32_t g_u[TOTU];

constexpr size_t OFF_HAF  = 0;
constexpr size_t OFF_DINV = OFF_HAF + (size_t)cN * cD;
constexpr size_t OFF_UTIL = OFF_DINV + cN;
constexpr size_t TOTF     = OFF_UTIL + 64;

__device__ __align__(16) float g_f[TOTF];

constexpr int ICNT = 0;
constexpr int ICUR = cN;
constexpr int IPTR = 2 * cN;
constexpr int ISRC = 3 * cN + 1;
constexpr int TOTI = 3 * cN + 1 + cE;

__device__ int g_i[TOTI];

// Packed bf16-pair weights: layout [z][N][K/2] uint32 (n-major, K-pairs)
constexpr size_t PW_IN  = 0;
constexpr size_t PW_MID = PW_IN  + (size_t)cF * cD / 2;
constexpr size_t PW_OUT = PW_MID + (size_t)cD * cD / 2;
constexpr size_t PW_FC1 = PW_OUT + (size_t)cD * cD / 2;
constexpr size_t PW_Q1  = PW_FC1 + (size_t)cD * cD / 2;
constexpr size_t PW_Q2  = PW_Q1  + 3ull * cD * cH / 2;
constexpr size_t PW_Q3  = PW_Q2  + 3ull * cH * cH / 2;
constexpr size_t TOTW   = PW_Q3  + 3ull * cH * cD / 2;

__device__ __align__(16) uint32_t g_w[TOTW];

// ---------------- small helpers ----------------------------------------------
__device__ __forceinline__ uint32_t pack_bf16(float lo, float hi) {
    __nv_bfloat162 v = __floats2bfloat162_rn(lo, hi);
    return *(uint32_t*)&v;
}

__device__ __forceinline__ float2 unpack_bf16(uint32_t u) {
    return __bfloat1622float2(*(__nv_bfloat162*)&u);
}

__device__ __forceinline__ void mma_bf16(float (&c)[4], const uint32_t (&a)[4],
                                         const uint32_t (&b)[2]) {
    asm volatile(
        "mma.sync.aligned.m16n8k16.row.col.f32.bf16.bf16.f32 "
        "{%0,%1,%2,%3},{%4,%5,%6,%7},{%8,%9},{%0,%1,%2,%3};"
        : "+f"(c[0]), "+f"(c[1]), "+f"(c[2]), "+f"(c[3])
        : "r"(a[0]), "r"(a[1]), "r"(a[2]), "r"(a[3]), "r"(b[0]), "r"(b[1]));
}

__device__ __forceinline__ void ldsm4(uint32_t (&r)[4], const uint32_t* p) {
    uint32_t a = (uint32_t)__cvta_generic_to_shared(p);
    asm volatile("ldmatrix.sync.aligned.m8n8.x4.shared.b16 {%0,%1,%2,%3}, [%4];"
                 : "=r"(r[0]), "=r"(r[1]), "=r"(r[2]), "=r"(r[3]) : "r"(a));
}

__device__ __forceinline__ void cp_async16(const void* smem_dst, const void* gsrc) {
    uint32_t d = (uint32_t)__cvta_generic_to_shared(smem_dst);
    asm volatile("cp.async.cg.shared.global [%0], [%1], 16;" :: "r"(d), "l"(gsrc)
                 : "memory");
}
#define CP_COMMIT() asm volatile("cp.async.commit_group;" ::: "memory")
#define CP_WAIT(n)  asm volatile("cp.async.wait_group %0;" :: "n"(n) : "memory")

// ---------------- utility kernels --------------------------------------------
constexpr int XPn = cN * cFw;
constexpr size_t PACK_TOT = (size_t)XPn + TOTW;
constexpr int ZN = 2 * cN;  // cnt + cur zeroing folded in
constexpr size_t PREP_TOT = PACK_TOT + ZN;

// One kernel: zero CSR counters + pack x + all weights into bf16-pair layouts.
__global__ void pack_all_kernel(const float* __restrict__ x,
                                const float* __restrict__ w_in,
                                const float* __restrict__ w_mid,
                                const float* __restrict__ w_out,
                                const float* __restrict__ fc1_w,
                                const float* __restrict__ q1,
                                const float* __restrict__ q2,
                                const float* __restrict__ q3,
                                uint32_t* __restrict__ XP,
                                uint32_t* __restrict__ Wb,
                                int* __restrict__ Iz) {
    size_t i = (size_t)blockIdx.x * blockDim.x + threadIdx.x;
    if (i >= PREP_TOT) return;
    if (i < (size_t)ZN) { Iz[i] = 0; return; }
    i -= ZN;
    if (i < (size_t)XPn) {
        XP[i] = pack_bf16(x[2 * i], x[2 * i + 1]);
        return;
    }
    size_t j = i - XPn;
    const float* W;
    size_t lo;
    int K, N;
    if (j < PW_MID)      { W = w_in;  lo = PW_IN;  K = cF; N = cD; }
    else if (j < PW_OUT) { W = w_mid; lo = PW_MID; K = cD; N = cD; }
    else if (j < PW_FC1) { W = w_out; lo = PW_OUT; K = cD; N = cD; }
    else if (j < PW_Q1)  { W = fc1_w; lo = PW_FC1; K = cD; N = cD; }
    else if (j < PW_Q2)  { W = q1;    lo = PW_Q1;  K = cD; N = cH; }
    else if (j < PW_Q3)  { W = q2;    lo = PW_Q2;  K = cH; N = cH; }
    else                 { W = q3;    lo = PW_Q3;  K = cH; N = cD; }
    size_t l = j - lo;
    int kp2 = K >> 1;
    int z = (int)(l / ((size_t)N * kp2));
    int rem = (int)(l - (size_t)z * N * kp2);
    int n = rem / kp2;
    int kp = rem - n * kp2;
    const float* Wz = W + (size_t)z * K * N;
    Wb[j] = pack_bf16(Wz[(size_t)(2 * kp) * N + n], Wz[(size_t)(2 * kp + 1) * N + n]);
}

__global__ void count_edges_kernel(const int* __restrict__ ei, int* __restrict__ cnt) {
    int e = blockIdx.x * blockDim.x + threadIdx.x;
    if (e < cE) atomicAdd(&cnt[ei[cE + e]], 1);
}

__global__ void scan_dinv_kernel(const int* __restrict__ cnt, int* __restrict__ ptr,
                                 float* __restrict__ dinv) {
    __shared__ int part[257];
    int t = threadIdx.x;
    int base = t * 32;
    int s = 0;
    for (int i = 0; i < 32; i++) s += cnt[base + i];
    part[t] = s;
    __syncthreads();
    if (t == 0) {
        int run = 0;
        for (int i = 0; i < 256; i++) { int v = part[i]; part[i] = run; run += v; }
        part[256] = run;
    }
    __syncthreads();
    int run = part[t];
    for (int i = 0; i < 32; i++) {
        int c = cnt[base + i];
        ptr[base + i] = run;
        run += c;
        dinv[base + i] = rsqrtf((float)c + 1.0f);
    }
    if (t == 0) ptr[cN] = part[256];
}

__global__ void fill_csr_kernel(const int* __restrict__ ei, const int* __restrict__ ptr,
                                int* __restrict__ cur, int* __restrict__ srcs) {
    int e = blockIdx.x * blockDim.x + threadIdx.x;
    if (e < cE) {
        int d = ei[cE + e];
        int p = atomicAdd(&cur[d], 1);
        srcs[ptr[d] + p] = ei[e];
    }
}

// ---------------- warp-MMA bf16 GEMM (3-stage cp.async, BK=64) ----------------
// Unchanged from R7 (measured at the HMMA issue ceiling).
constexpr int GEMM_DYN = 3 * 2 * 128 * 36 * 4;  // 110592 bytes

template <int ACT, int OUTF>
__global__ __launch_bounds__(256) void gemm_wm(
    const uint32_t* __restrict__ Ap, const uint32_t* __restrict__ Wp,
    const float* __restrict__ bias, void* __restrict__ Cout,
    int Kp2, int N, size_t sA, size_t sW, size_t sB, size_t sC) {
    extern __shared__ __align__(16) uint32_t sh[];
    uint32_t(*As)[128][36] = (uint32_t(*)[128][36])sh;
    uint32_t(*Bs)[128][36] = (uint32_t(*)[128][36])(sh + 3 * 128 * 36);

    int z = blockIdx.z;
    Ap += z * sA;
    Wp += z * sW;
    const float* bz = bias ? bias + z * sB : nullptr;

    int tid = threadIdx.x;
    int lane = tid & 31, warp = tid >> 5;
    int wm = warp & 3, wn = warp >> 2;  // 4 x 2 warp grid
    int g = lane >> 2, q4 = lane & 3;

    int rowB = blockIdx.y * 128;
    int colB = blockIdx.x * 128;

    int a_ro = ((lane >> 3) & 1) * 8 + (lane & 7);
    int a_co = (lane >> 4) * 4;
    int b_ro = ((lane >> 4) << 3) + (lane & 7);
    int b_co = ((lane >> 3) & 1) * 4;

    int srow = tid >> 1, sw0 = (tid & 1) * 16;

    auto stage = [&](int buf, int kt) {
        const uint32_t* as = &Ap[(size_t)(rowB + srow) * Kp2 + kt * 32 + sw0];
        const uint32_t* bs = &Wp[(size_t)(colB + srow) * Kp2 + kt * 32 + sw0];
#pragma unroll
        for (int i = 0; i < 4; i++) {
            cp_async16(&As[buf][srow][sw0 + 4 * i], as + 4 * i);
            cp_async16(&Bs[buf][srow][sw0 + 4 * i], bs + 4 * i);
        }
        CP_COMMIT();
    };

    float acc[2][8][4] = {};

    int KT = Kp2 >> 5;
    stage(0, 0);
    stage(1, 1);

    for (int kt = 0; kt < KT; kt++) {
        int cur = kt % 3;
        if (kt + 1 < KT) CP_WAIT(1);
        else             CP_WAIT(0);
        __syncthreads();
        if (kt + 2 < KT) stage((kt + 2) % 3, kt + 2);
#pragma unroll
        for (int c = 0; c < 4; c++) {
            uint32_t af[2][4];
            ldsm4(af[0], &As[cur][wm * 32 + a_ro][c * 8 + a_co]);
            ldsm4(af[1], &As[cur][wm * 32 + 16 + a_ro][c * 8 + a_co]);
            uint32_t bf[8][2];
#pragma unroll
            for (int nt2 = 0; nt2 < 4; nt2++) {
                uint32_t r[4];
                ldsm4(r, &Bs[cur][wn * 64 + nt2 * 16 + b_ro][c * 8 + b_co]);
                bf[2 * nt2][0] = r[0]; bf[2 * nt2][1] = r[1];
                bf[2 * nt2 + 1][0] = r[2]; bf[2 * nt2 + 1][1] = r[3];
            }
#pragma unroll
            for (int mt = 0; mt < 2; mt++)
#pragma unroll
                for (int nt = 0; nt < 8; nt++) mma_bf16(acc[mt][nt], af[mt], bf[nt]);
        }
    }

#pragma unroll
    for (int mt = 0; mt < 2; mt++) {
#pragma unroll
        for (int nt = 0; nt < 8; nt++) {
            int r0 = rowB + wm * 32 + mt * 16 + g;
            int c = colB + wn * 64 + nt * 8 + q4 * 2;
            float v00 = acc[mt][nt][0], v01 = acc[mt][nt][1];
            float v10 = acc[mt][nt][2], v11 = acc[mt][nt][3];
            if (bz) {
                float b0 = bz[c], b1 = bz[c + 1];
                v00 += b0; v01 += b1; v10 += b0; v11 += b1;
            }
            if (ACT == 1) {
                v00 = fmaxf(v00, 0.f); v01 = fmaxf(v01, 0.f);
                v10 = fmaxf(v10, 0.f); v11 = fmaxf(v11, 0.f);
            } else if (ACT == 2) {
                v00 = tanhf(v00); v01 = tanhf(v01);
                v10 = tanhf(v10); v11 = tanhf(v11);
            }
            if (OUTF == 1) {
                uint32_t* Cw = (uint32_t*)Cout + z * sC;
                Cw[(size_t)r0 * (N >> 1) + (c >> 1)] = pack_bf16(v00, v01);
                Cw[(size_t)(r0 + 8) * (N >> 1) + (c >> 1)] = pack_bf16(v10, v11);
            } else {
                float* Cf = (float*)Cout + z * sC;
                float2 p0 = {v00, v01};
                float2 p1 = {v10, v11};
                *(float2*)&Cf[(size_t)r0 * N + c] = p0;
                *(float2*)&Cf[(size_t)(r0 + 8) * N + c] = p1;
            }
        }
    }
}

// ---------------- GCN aggregation (packed bf16, index-prefetch chunks) --------
__global__ __launch_bounds__(128) void gcn_agg_tanh(
    const uint32_t* __restrict__ xw, const float* __restrict__ bias,
    const int* __restrict__ ptr, const int* __restrict__ srcs,
    const float* __restrict__ dinv, uint32_t* __restrict__ out) {
    __shared__ int sidx[32];
    int i = blockIdx.x;
    int tid = threadIdx.x;
    int w0 = tid * 2;
    float di = dinv[i];
    float4 bv = *(const float4*)&bias[w0 * 2];
    uint2 xv = *(const uint2*)&xw[(size_t)i * cDw + w0];
    float2 x0 = unpack_bf16(xv.x), x1 = unpack_bf16(xv.y);
    float ns = di * di;
    float a0 = bv.x + ns * x0.x;
    float a1 = bv.y + ns * x0.y;
    float a2 = bv.z + ns * x1.x;
    float a3 = bv.w + ns * x1.y;
    int s = ptr[i], e = ptr[i + 1];
    for (int base = s; base < e; base += 32) {
        int m = min(32, e - base);
        __syncthreads();
        if (tid < m) sidx[tid] = srcs[base + tid];
        __syncthreads();
#pragma unroll 4
        for (int k = 0; k < m; k++) {
            int r = sidx[k];
            float w = di * dinv[r];
            uint2 v = *(const uint2*)&xw[(size_t)r * cDw + w0];
            float2 v0 = unpack_bf16(v.x), v1 = unpack_bf16(v.y);
            a0 += w * v0.x; a1 += w * v0.y; a2 += w * v1.x; a3 += w * v1.y;
        }
    }
    out[(size_t)i * cDw + w0] = pack_bf16(tanhf(a0), tanhf(a1));
    out[(size_t)i * cDw + w0 + 1] = pack_bf16(tanhf(a2), tanhf(a3));
}

// ---------------- tensor-core pair attention (64-query blocks, grid=128) ------
// Block = (pair, half, q-subtile): 64 queries x 128 cross-doc keys, D=512.
// Static smem (35840 B): phase1 Qs[64][36]+Ks[128][36]; phase2/3 P[64][68]+
// Vs[64][68]+stats[4][64].
constexpr int AT_KS = 64 * 36;
constexpr int AT_VS = 64 * 68;
constexpr int AT_ST = 2 * 64 * 68;
constexpr int AT_W  = AT_ST + 256;

__global__ __launch_bounds__(256) void attn_tc(const uint32_t* __restrict__ qkv,
                                               uint32_t* __restrict__ out) {
    __shared__ __align__(16) uint32_t sm[AT_W];
    uint32_t(*Qs)[36] = (uint32_t(*)[36])sm;
    uint32_t(*Ks)[36] = (uint32_t(*)[36])(sm + AT_KS);
    uint32_t(*P)[68] = (uint32_t(*)[68])sm;
    uint32_t(*Vs)[68] = (uint32_t(*)[68])(sm + AT_VS);
    float* stats = (float*)(sm + AT_ST);  // [4][64]

    const uint32_t* Q = qkv;
    const uint32_t* Kx = qkv + (size_t)cN * cDw;
    const uint32_t* V = qkv + 2 * (size_t)cN * cDw;

    int bx = blockIdx.x;
    int p = bx >> 2, h = (bx >> 1) & 1, sq = bx & 1;
    int q0 = p * 256 + h * 128 + sq * 64;
    int k0 = p * 256 + (h ^ 1) * 128;

    int tid = threadIdx.x;
    int lane = tid & 31, warp = tid >> 5;
    int wm = warp & 1, wn = warp >> 1;  // 2 x 4 warp grid
    int g = lane >> 2, q4 = lane & 3;

    int a_ro = ((lane >> 3) & 1) * 8 + (lane & 7);
    int a_co = (lane >> 4) * 4;
    int b_ro = ((lane >> 4) << 3) + (lane & 7);
    int b_co = ((lane >> 3) & 1) * 4;

    // ---- phase 1: S = Q K^T (64x128) over 8 chunks of 64 dims ----
    float acc[2][4][4] = {};
    int qrow = tid >> 2, qw = (tid & 3) * 8;
    int krow = tid >> 1, kw = (tid & 1) * 16;
    for (int dc = 0; dc < 8; dc++) {
        {
            const uint32_t* qp = &Q[(size_t)(q0 + qrow) * cDw + dc * 32 + qw];
            *(uint4*)&Qs[qrow][qw] = *(const uint4*)&qp[0];
            *(uint4*)&Qs[qrow][qw + 4] = *(const uint4*)&qp[4];
            const uint32_t* kp = &Kx[(size_t)(k0 + krow) * cDw + dc * 32 + kw];
#pragma unroll
            for (int i2 = 0; i2 < 4; i2++)
                *(uint4*)&Ks[krow][kw + 4 * i2] = *(const uint4*)&kp[4 * i2];
        }
        __syncthreads();
#pragma unroll
        for (int c = 0; c < 4; c++) {
            uint32_t af[2][4];
            ldsm4(af[0], &Qs[wm * 32 + a_ro][c * 8 + a_co]);
            ldsm4(af[1], &Qs[wm * 32 + 16 + a_ro][c * 8 + a_co]);
            uint32_t bf[4][2];
#pragma unroll
            for (int nt2 = 0; nt2 < 2; nt2++) {
                uint32_t r[4];
                ldsm4(r, &Ks[wn * 32 + nt2 * 16 + b_ro][c * 8 + b_co]);
                bf[2 * nt2][0] = r[0]; bf[2 * nt2][1] = r[1];
                bf[2 * nt2 + 1][0] = r[2]; bf[2 * nt2 + 1][1] = r[3];
            }
#pragma unroll
            for (int mt = 0; mt < 2; mt++)
#pragma unroll
                for (int nt = 0; nt < 4; nt++) mma_bf16(acc[mt][nt], af[mt], bf[nt]);
        }
        __syncthreads();
    }

    // ---- phase 2: softmax over 128 keys per query (4-way warp combine) ----
    constexpr float scale = 0.0441941738241592f;  // 1/sqrt(512)
#pragma unroll
    for (int mt = 0; mt < 2; mt++)
#pragma unroll
        for (int nt = 0; nt < 4; nt++)
#pragma unroll
            for (int j = 0; j < 4; j++) acc[mt][nt][j] *= scale;

#pragma unroll
    for (int mt = 0; mt < 2; mt++) {
        float m0 = -1e30f, m1 = -1e30f;
#pragma unroll
        for (int nt = 0; nt < 4; nt++) {
            m0 = fmaxf(m0, fmaxf(acc[mt][nt][0], acc[mt][nt][1]));
            m1 = fmaxf(m1, fmaxf(acc[mt][nt][2], acc[mt][nt][3]));
        }
#pragma unroll
        for (int d = 1; d < 4; d <<= 1) {
            m0 = fmaxf(m0, __shfl_xor_sync(0xffffffffu, m0, d));
            m1 = fmaxf(m1, __shfl_xor_sync(0xffffffffu, m1, d));
        }
        if (q4 == 0) {
            int r = wm * 32 + mt * 16 + g;
            stats[wn * 64 + r] = m0;
            stats[wn * 64 + r + 8] = m1;
        }
    }
    __syncthreads();
    float rmax[2][2], rsum[2][2];
#pragma unroll
    for (int mt = 0; mt < 2; mt++) {
        int r = wm * 32 + mt * 16 + g;
        float u0 = fmaxf(fmaxf(stats[r], stats[64 + r]),
                         fmaxf(stats[128 + r], stats[192 + r]));
        float u1 = fmaxf(fmaxf(stats[r + 8], stats[64 + r + 8]),
                         fmaxf(stats[128 + r + 8], stats[192 + r + 8]));
        rmax[mt][0] = u0; rmax[mt][1] = u1;
    }
#pragma unroll
    for (int mt = 0; mt < 2; mt++) {
        float s0 = 0.f, s1 = 0.f;
#pragma unroll
        for (int nt = 0; nt < 4; nt++) {
            acc[mt][nt][0] = __expf(acc[mt][nt][0] - rmax[mt][0]);
            acc[mt][nt][1] = __expf(acc[mt][nt][1] - rmax[mt][0]);
            acc[mt][nt][2] = __expf(acc[mt][nt][2] - rmax[mt][1]);
            acc[mt][nt][3] = __expf(acc[mt][nt][3] - rmax[mt][1]);
            s0 += acc[mt][nt][0] + acc[mt][nt][1];
            s1 += acc[mt][nt][2] + acc[mt][nt][3];
        }
#pragma unroll
        for (int d = 1; d < 4; d <<= 1) {
            s0 += __shfl_xor_sync(0xffffffffu, s0, d);
            s1 += __shfl_xor_sync(0xffffffffu, s1, d);
        }
        rsum[mt][0] = s0; rsum[mt][1] = s1;
    }
    __syncthreads();  // max reads complete before stats reuse
#pragma unroll
    for (int mt = 0; mt < 2; mt++) {
        if (q4 == 0) {
            int r = wm * 32 + mt * 16 + g;
            stats[wn * 64 + r] = rsum[mt][0];
            stats[wn * 64 + r + 8] = rsum[mt][1];
        }
    }
    __syncthreads();
#pragma unroll
    for (int mt = 0; mt < 2; mt++) {
        int r = wm * 32 + mt * 16 + g;
        float i0 = 1.0f / (stats[r] + stats[64 + r] + stats[128 + r] + stats[192 + r]);
        float i1 = 1.0f / (stats[r + 8] + stats[64 + r + 8] + stats[128 + r + 8] +
                           stats[192 + r + 8]);
#pragma unroll
        for (int nt = 0; nt < 4; nt++) {
            int kp = wn * 16 + nt * 4 + q4;
            P[r][kp] = pack_bf16(acc[mt][nt][0] * i0, acc[mt][nt][1] * i0);
            P[r + 8][kp] = pack_bf16(acc[mt][nt][2] * i1, acc[mt][nt][3] * i1);
        }
    }
    __syncthreads();

    // ---- phase 3: O = P V (64 x 512), 8 chunks of 64 dims ----
    int vkp = tid >> 2, vd0 = (tid & 3) * 16;
    for (int nc = 0; nc < 8; nc++) {
        {
            const uint32_t* v0 = &V[(size_t)(k0 + 2 * vkp) * cDw + nc * 32 + (tid & 3) * 8];
            const uint32_t* v1 = v0 + cDw;
#pragma unroll
            for (int j = 0; j < 8; j++) {
                uint32_t a = v0[j], b = v1[j];
                Vs[vd0 + 2 * j][vkp] = __byte_perm(a, b, 0x5410);
                Vs[vd0 + 2 * j + 1][vkp] = __byte_perm(a, b, 0x7632);
            }
        }
        __syncthreads();
        float o[2][2][4] = {};
#pragma unroll
        for (int c = 0; c < 8; c++) {
            uint32_t af[2][4];
            ldsm4(af[0], &P[wm * 32 + a_ro][c * 8 + a_co]);
            ldsm4(af[1], &P[wm * 32 + 16 + a_ro][c * 8 + a_co]);
            uint32_t r[4];
            ldsm4(r, &Vs[wn * 16 + b_ro][c * 8 + b_co]);
            uint32_t bf[2][2];
            bf[0][0] = r[0]; bf[0][1] = r[1];
            bf[1][0] = r[2]; bf[1][1] = r[3];
#pragma unroll
            for (int mt = 0; mt < 2; mt++)
#pragma unroll
                for (int nt = 0; nt < 2; nt++) mma_bf16(o[mt][nt], af[mt], bf[nt]);
        }
#pragma unroll
        for (int mt = 0; mt < 2; mt++)
#pragma unroll
            for (int nt = 0; nt < 2; nt++) {
                int r = q0 + wm * 32 + mt * 16 + g;
                int widx = nc * 32 + wn * 8 + nt * 4 + q4;
                out[(size_t)r * cDw + widx] = pack_bf16(o[mt][nt][0], o[mt][nt][1]);
                out[(size_t)(r + 8) * cDw + widx] = pack_bf16(o[mt][nt][2], o[mt][nt][3]);
            }
        __syncthreads();
    }
}

// ---------------- fc2 (tanh) -> fc3 -> per-doc mean-pool sums ----------------
__global__ __launch_bounds__(256) void fc2pool(
    const float* __restrict__ h, const float* __restrict__ w2,
    const float* __restrict__ b2, const float* __restrict__ w3,
    const float* __restrict__ b3, float* __restrict__ util) {
    int lane = threadIdx.x & 31, wy = threadIdx.x >> 5;
    int r = blockIdx.x * 8 + wy;
    const float* hr = h + (size_t)r * cD;
    float a = b2[lane];
#pragma unroll 4
    for (int k = 0; k < cD; k += 4) {
        float4 hv = *(const float4*)&hr[k];
        a += hv.x * w2[(k + 0) * 32 + lane];
        a += hv.y * w2[(k + 1) * 32 + lane];
        a += hv.z * w2[(k + 2) * 32 + lane];
        a += hv.w * w2[(k + 3) * 32 + lane];
    }
    a = tanhf(a);
    float pc = a * w3[lane];
#pragma unroll
    for (int off = 16; off; off >>= 1) pc += __shfl_xor_sync(0xffffffffu, pc, off);
    if (lane == 0) atomicAdd(&util[r >> 7], pc + b3[0]);
}

__global__ void zero_f_kernel(float* p, int n) {
    int i = blockIdx.x * blockDim.x + threadIdx.x;
    if (i < n) p[i] = 0.0f;
}

__global__ void final_kernel(const float* __restrict__ util, const int* __restrict__ ia,
                             const int* __restrict__ ib, float* __restrict__ out) {
    int p = threadIdx.x;
    if (p < 32) {
        float d = (util[ib[p]] - util[ia[p]]) * (1.0f / 128.0f);
        out[p] = 1.0f / (1.0f + __expf(-d));
    }
}

// ---------------- launch orchestration ---------------------------------------
extern "C" void kernel_launch(void* const* d_in, const int* in_sizes, int n_in,
                              void* d_out, int out_size) {
    const float* x      = (const float*)d_in[0];
    const float* b_in   = (const float*)d_in[2];
    const float* b_mid  = (const float*)d_in[4];
    const float* b_out  = (const float*)d_in[6];
    const float* fc1_b  = (const float*)d_in[8];
    const float* fc2_w  = (const float*)d_in[9];
    const float* fc2_b  = (const float*)d_in[10];
    const float* fc3_w  = (const float*)d_in[11];
    const float* fc3_b  = (const float*)d_in[12];
    const float* qkv1_b = (const float*)d_in[14];
    const float* qkv2_b = (const float*)d_in[16];
    const float* qkv3_b = (const float*)d_in[18];
    const int* ei       = (const int*)d_in[19];
    const int* idx_a    = (const int*)d_in[22];
    const int* idx_b    = (const int*)d_in[23];

    float* F;
    int* I;
    uint32_t* Wb;
    uint32_t* U;
    cudaGetSymbolAddress((void**)&F, g_f);
    cudaGetSymbolAddress((void**)&I, g_i);
    cudaGetSymbolAddress((void**)&Wb, g_w);
    cudaGetSymbolAddress((void**)&U, g_u);

    cudaFuncSetAttribute(gemm_wm<0, 1>, cudaFuncAttributeMaxDynamicSharedMemorySize, GEMM_DYN);
    cudaFuncSetAttribute(gemm_wm<1, 1>, cudaFuncAttributeMaxDynamicSharedMemorySize, GEMM_DYN);
    cudaFuncSetAttribute(gemm_wm<2, 0>, cudaFuncAttributeMaxDynamicSharedMemorySize, GEMM_DYN);

    uint32_t* XP   = U + UP_XP;
    uint32_t* HP   = U + UP_H;
    uint32_t* XWP  = U + UP_XW;
    uint32_t* HAP  = U + UP_HA;
    uint32_t* T1P  = U + UP_T1;
    uint32_t* T2P  = U + UP_T2;
    uint32_t* QKVP = U + UP_QKV;
    float* HAF  = F + OFF_HAF;
    float* DINV = F + OFF_DINV;
    float* UTIL = F + OFF_UTIL;

    // ---- prep (4 launches) ----
    pack_all_kernel<<<(int)((PREP_TOT + 255) / 256), 256>>>(
        x, (const float*)d_in[1], (const float*)d_in[3], (const float*)d_in[5],
        (const float*)d_in[7], (const float*)d_in[13], (const float*)d_in[15],
        (const float*)d_in[17], XP, Wb, I + ICNT);
    count_edges_kernel<<<cE / 256, 256>>>(ei, I + ICNT);
    scan_dinv_kernel<<<1, 256>>>(I + ICNT, I + IPTR, DINV);
    fill_csr_kernel<<<cE / 256, 256>>>(ei, I + IPTR, I + ICUR, I + ISRC);

    const uint32_t* winp[4] = {Wb + PW_IN, Wb + PW_MID, Wb + PW_MID, Wb + PW_OUT};
    const float*    bin[4]  = {b_in, b_mid, b_mid, b_out};

    for (int layer = 0; layer < 4; layer++) {
        const uint32_t* hin = (layer == 0) ? XP : HP;
        int Kp2 = (layer == 0) ? cFw : cDw;
        gemm_wm<0, 1><<<dim3(cD / 128, cN / 128, 1), 256, GEMM_DYN>>>(
            hin, winp[layer], nullptr, XWP, Kp2, cD, 0, 0, 0, 0);
        gcn_agg_tanh<<<cN, 128>>>(XWP, bin[layer], I + IPTR, I + ISRC, DINV, HAP);
        gemm_wm<1, 1><<<dim3(cH / 128, cN / 128, 3), 256, GEMM_DYN>>>(
            HAP, Wb + PW_Q1, qkv1_b, T1P, cDw, cH,
            0, (size_t)cH * cDw, cH, (size_t)cN * cHw);
        gemm_wm<1, 1><<<dim3(cH / 128, cN / 128, 3), 256, GEMM_DYN>>>(
            T1P, Wb + PW_Q2, qkv2_b, T2P, cHw, cH,
            (size_t)cN * cHw, (size_t)cH * cHw, cH, (size_t)cN * cHw);
        gemm_wm<1, 1><<<dim3(cD / 128, cN / 128, 3), 256, GEMM_DYN>>>(
            T2P, Wb + PW_Q3, qkv3_b, QKVP, cHw, cD,
            (size_t)cN * cHw, (size_t)cD * cHw, cD, (size_t)cN * cDw);
        attn_tc<<<128, 256>>>(QKVP, HP);
    }

    // ---- head ----
    gemm_wm<2, 0><<<dim3(cD / 128, cN / 128, 1), 256, GEMM_DYN>>>(
        HP, Wb + PW_FC1, fc1_b, HAF, cDw, cD, 0, 0, 0, 0);
    zero_f_kernel<<<1, 64>>>(UTIL, 64);
    fc2pool<<<cN / 8, 256>>>(HAF, fc2_w, fc2_b, fc3_w, fc3_b, UTIL);
    final_kernel<<<1, 32>>>(UTIL, idx_a, idx_b, (float*)d_out);
}